// round 2
// baseline (speedup 1.0000x reference)
#include <cuda_runtime.h>
#include <cuda_bf16.h>
#include <math.h>

// Problem constants
constexpr int Bb   = 32;          // batch
constexpr int HW   = 1024;        // H*W tokens per batch
constexpr int C    = 512;         // channels
constexpr int G    = 8;           // groups
constexpr int CG   = C / G;       // 64 channels per group
constexpr int NTOK = Bb * HW;     // 32768 total tokens
constexpr int QKVN = 3 * C;       // 1536
constexpr float EPS = 1e-3f;

// Scratch (device globals -> allowed; no allocations). 384 MB total.
// g_h doubles as: normalized input (pre-QKV), then attention output (post-AV).
__device__ float g_h [ (long)NTOK * C ];           // 64 MB
__device__ float g_q [ (long)NTOK * C ];           // 64 MB
__device__ float g_k [ (long)NTOK * C ];           // 64 MB
__device__ float g_v [ (long)NTOK * C ];           // 64 MB
__device__ float g_scores[ (long)Bb * HW * HW ];   // 128 MB

// ---------------------------------------------------------------------------
// GroupNorm: one block per (batch, group). 1024 tokens * 64 ch = 65536 elems.
// ---------------------------------------------------------------------------
__global__ void groupnorm_kernel(const float* __restrict__ x,
                                 const float* __restrict__ gamma,
                                 const float* __restrict__ beta)
{
    const int bg = blockIdx.x;          // 0..255
    const int b  = bg >> 3;
    const int g  = bg & 7;
    const int t  = threadIdx.x;         // 256 threads

    const long base = ((long)b * HW) * C + g * CG;

    __shared__ float s_sum[256];
    __shared__ float s_sq [256];

    float lsum = 0.f, lsq = 0.f;
    for (int idx = t; idx < HW * CG; idx += 256) {
        int n = idx >> 6;           // token
        int c = idx & 63;           // channel within group
        float v = x[base + (long)n * C + c];
        lsum += v;
        lsq  += v * v;
    }
    s_sum[t] = lsum; s_sq[t] = lsq;
    __syncthreads();
    for (int s = 128; s > 0; s >>= 1) {
        if (t < s) { s_sum[t] += s_sum[t + s]; s_sq[t] += s_sq[t + s]; }
        __syncthreads();
    }
    const float inv_n = 1.0f / (HW * CG);
    const float mean  = s_sum[0] * inv_n;
    const float var   = s_sq[0] * inv_n - mean * mean;
    const float rstd  = rsqrtf(var + EPS);

    for (int idx = t; idx < HW * CG; idx += 256) {
        int n = idx >> 6;
        int c = idx & 63;
        int gc = g * CG + c;
        float v = x[base + (long)n * C + c];
        g_h[base + (long)n * C + c] = (v - mean) * rstd * gamma[gc] + beta[gc];
    }
}

// ---------------------------------------------------------------------------
// Shared tiled SGEMM core: BM=BN=128, BK=8, 256 threads, 8x8 microtile.
// NT=false: C = A[M,K] * B[K,N]   (B row-major, ldb = row stride)
// NT=true : C = A[M,K] * B[N,K]^T (B row-major [N,K])
// A must already be offset to the block's m0 row; B offset per caller.
// All dims assumed multiples of the tile sizes (true for this problem).
// ---------------------------------------------------------------------------
constexpr int BM = 128, BN = 128, BK = 8, TM = 8, TN = 8;

template<bool NT>
__device__ __forceinline__ void gemm_core(const float* __restrict__ A,
                                          const float* __restrict__ B,
                                          int K, int lda, int ldb,
                                          float acc[TM][TN])
{
    __shared__ float As[BK][BM];
    __shared__ float Bs[BK][BN];

    const int tid  = threadIdx.x;
    const int tx   = tid & 15;       // 0..15
    const int ty   = tid >> 4;       // 0..15
    const int lrow = tid >> 1;       // 0..127 (for A and NT-B loads)
    const int lcol = (tid & 1) * 4;  // 0 or 4
    const int brow = tid >> 5;       // 0..7   (for NN-B loads)
    const int bcol = (tid & 31) * 4; // 0..124

    for (int k0 = 0; k0 < K; k0 += BK) {
        float4 av = *reinterpret_cast<const float4*>(&A[(long)lrow * lda + k0 + lcol]);
        As[lcol + 0][lrow] = av.x;
        As[lcol + 1][lrow] = av.y;
        As[lcol + 2][lrow] = av.z;
        As[lcol + 3][lrow] = av.w;
        if (NT) {
            float4 bv = *reinterpret_cast<const float4*>(&B[(long)lrow * ldb + k0 + lcol]);
            Bs[lcol + 0][lrow] = bv.x;
            Bs[lcol + 1][lrow] = bv.y;
            Bs[lcol + 2][lrow] = bv.z;
            Bs[lcol + 3][lrow] = bv.w;
        } else {
            float4 bv = *reinterpret_cast<const float4*>(&B[(long)(k0 + brow) * ldb + bcol]);
            *reinterpret_cast<float4*>(&Bs[brow][bcol]) = bv;
        }
        __syncthreads();
        #pragma unroll
        for (int kk = 0; kk < BK; kk++) {
            float a[TM], bb[TN];
            #pragma unroll
            for (int i = 0; i < TM; i++) a[i]  = As[kk][ty * TM + i];
            #pragma unroll
            for (int j = 0; j < TN; j++) bb[j] = Bs[kk][tx * TN + j];
            #pragma unroll
            for (int i = 0; i < TM; i++)
                #pragma unroll
                for (int j = 0; j < TN; j++)
                    acc[i][j] = fmaf(a[i], bb[j], acc[i][j]);
        }
        __syncthreads();
    }
}

// ---------------------------------------------------------------------------
// QKV GEMM: [NTOK,512] x [512,1536] + bias, scattered into g_q/g_k/g_v.
// Each 128-wide N tile lies entirely inside one of q/k/v (512 % 128 == 0).
// ---------------------------------------------------------------------------
__global__ void qkv_gemm_kernel(const float* __restrict__ w,
                                const float* __restrict__ bias)
{
    const int n0 = blockIdx.x * BN;
    const int m0 = blockIdx.y * BM;
    float acc[TM][TN] = {};
    gemm_core<false>(g_h + (long)m0 * C, w + n0, C, C, QKVN, acc);

    const int tx = threadIdx.x & 15, ty = threadIdx.x >> 4;
    const int which = n0 >> 9;   // 0=q 1=k 2=v (constant per block)
    float* dst = (which == 0) ? g_q : (which == 1) ? g_k : g_v;
    #pragma unroll
    for (int i = 0; i < TM; i++) {
        const int m = m0 + ty * TM + i;
        #pragma unroll
        for (int j = 0; j < TN; j++) {
            const int n = n0 + tx * TN + j;
            const int c = n & 511;
            dst[(long)m * C + c] = acc[i][j] + bias[n];
        }
    }
}

// ---------------------------------------------------------------------------
// scores[b,n,m] = scale * sum_c q[b,n,c] * k[b,m,c]   (NT GEMM, batched)
// ---------------------------------------------------------------------------
__global__ void scores_kernel()
{
    const int b  = blockIdx.z;
    const int n0 = blockIdx.x * BN;   // key-tile
    const int m0 = blockIdx.y * BM;   // query-tile
    const float scale = rsqrtf((float)C);

    const float* q = g_q + (long)b * HW * C;
    const float* k = g_k + (long)b * HW * C;
    float acc[TM][TN] = {};
    gemm_core<true>(q + (long)m0 * C, k + (long)n0 * C, C, C, C, acc);

    float* out = g_scores + (long)b * HW * HW;
    const int tx = threadIdx.x & 15, ty = threadIdx.x >> 4;
    #pragma unroll
    for (int i = 0; i < TM; i++) {
        const int m = m0 + ty * TM + i;
        #pragma unroll
        for (int j = 0; j < TN; j++) {
            const int n = n0 + tx * TN + j;
            out[(long)m * HW + n] = acc[i][j] * scale;
        }
    }
}

// ---------------------------------------------------------------------------
// Row softmax over 1024 entries. One block per row, 256 threads x 4 values.
// ---------------------------------------------------------------------------
__global__ void softmax_kernel()
{
    __shared__ float red[256];
    float* p = g_scores + (long)blockIdx.x * HW;
    const int t = threadIdx.x;

    float v0 = p[t], v1 = p[t + 256], v2 = p[t + 512], v3 = p[t + 768];
    float mx = fmaxf(fmaxf(v0, v1), fmaxf(v2, v3));
    red[t] = mx; __syncthreads();
    for (int s = 128; s > 0; s >>= 1) {
        if (t < s) red[t] = fmaxf(red[t], red[t + s]);
        __syncthreads();
    }
    mx = red[0];
    __syncthreads();

    v0 = __expf(v0 - mx); v1 = __expf(v1 - mx);
    v2 = __expf(v2 - mx); v3 = __expf(v3 - mx);
    red[t] = v0 + v1 + v2 + v3; __syncthreads();
    for (int s = 128; s > 0; s >>= 1) {
        if (t < s) red[t] += red[t + s];
        __syncthreads();
    }
    const float inv = 1.0f / red[0];
    p[t]       = v0 * inv;
    p[t + 256] = v1 * inv;
    p[t + 512] = v2 * inv;
    p[t + 768] = v3 * inv;
}

// ---------------------------------------------------------------------------
// attention output: g_h[b,n,c] = sum_m attn[b,n,m] * v[b,m,c]  (NN, batched)
// (g_h is dead after the QKV GEMM, so it is reused as the AV output buffer.)
// ---------------------------------------------------------------------------
__global__ void av_kernel()
{
    const int b  = blockIdx.z;
    const int n0 = blockIdx.x * BN;   // channel tile (512/128 = 4)
    const int m0 = blockIdx.y * BM;   // query tile
    const float* attn = g_scores + (long)b * HW * HW;
    const float* v    = g_v      + (long)b * HW * C;

    float acc[TM][TN] = {};
    gemm_core<false>(attn + (long)m0 * HW, v + n0, HW, HW, C, acc);

    float* out = g_h + (long)b * HW * C;
    const int tx = threadIdx.x & 15, ty = threadIdx.x >> 4;
    #pragma unroll
    for (int i = 0; i < TM; i++) {
        const int m = m0 + ty * TM + i;
        #pragma unroll
        for (int j = 0; j < TN; j++) {
            const int n = n0 + tx * TN + j;
            out[(long)m * C + n] = acc[i][j];
        }
    }
}

// ---------------------------------------------------------------------------
// proj + bias + residual: out = x + g_h @ w_proj + b_proj
// ---------------------------------------------------------------------------
__global__ void proj_kernel(const float* __restrict__ x,
                            const float* __restrict__ w,
                            const float* __restrict__ bias,
                            float* __restrict__ out)
{
    const int n0 = blockIdx.x * BN;
    const int m0 = blockIdx.y * BM;
    float acc[TM][TN] = {};
    gemm_core<false>(g_h + (long)m0 * C, w + n0, C, C, C, acc);

    const int tx = threadIdx.x & 15, ty = threadIdx.x >> 4;
    #pragma unroll
    for (int i = 0; i < TM; i++) {
        const int m = m0 + ty * TM + i;
        #pragma unroll
        for (int j = 0; j < TN; j++) {
            const int n = n0 + tx * TN + j;
            out[(long)m * C + n] = acc[i][j] + bias[n] + x[(long)m * C + n];
        }
    }
}

// ---------------------------------------------------------------------------
extern "C" void kernel_launch(void* const* d_in, const int* in_sizes, int n_in,
                              void* d_out, int out_size)
{
    const float* x      = (const float*)d_in[0];
    const float* gamma  = (const float*)d_in[1];
    const float* beta   = (const float*)d_in[2];
    const float* w_qkv  = (const float*)d_in[3];
    const float* b_qkv  = (const float*)d_in[4];
    const float* w_proj = (const float*)d_in[5];
    const float* b_proj = (const float*)d_in[6];
    float* out = (float*)d_out;

    groupnorm_kernel<<<Bb * G, 256>>>(x, gamma, beta);
    qkv_gemm_kernel<<<dim3(QKVN / BN, NTOK / BM), 256>>>(w_qkv, b_qkv);
    scores_kernel<<<dim3(HW / BN, HW / BM, Bb), 256>>>();
    softmax_kernel<<<Bb * HW, 256>>>();
    av_kernel<<<dim3(C / BN, HW / BM, Bb), 256>>>();
    proj_kernel<<<dim3(C / BN, NTOK / BM), 256>>>(x, w_proj, b_proj, out);
}

// round 4
// speedup vs baseline: 1.6630x; 1.6630x over previous
#include <cuda_runtime.h>
#include <cuda_bf16.h>
#include <math.h>

// Problem constants
constexpr int Bb   = 32;          // batch
constexpr int HW   = 1024;        // H*W tokens per batch
constexpr int C    = 512;         // channels
constexpr int G    = 8;           // groups
constexpr int CG   = C / G;       // 64 channels per group
constexpr int NTOK = Bb * HW;     // 32768 total tokens
constexpr int QKVN = 3 * C;       // 1536
constexpr float EPS = 1e-3f;

// Scratch (device globals -> allowed; no allocations). 384 MB total.
// g_h doubles as: normalized input (pre-QKV), then attention output (post-AV).
__device__ float g_h [ (long)NTOK * C ];           // 64 MB
__device__ float g_q [ (long)NTOK * C ];           // 64 MB
__device__ float g_k [ (long)NTOK * C ];           // 64 MB
__device__ float g_v [ (long)NTOK * C ];           // 64 MB
__device__ float g_scores[ (long)Bb * HW * HW ];   // 128 MB

// ---------------------------------------------------------------------------
// GroupNorm: one block per (batch, group).
// ---------------------------------------------------------------------------
__global__ void groupnorm_kernel(const float* __restrict__ x,
                                 const float* __restrict__ gamma,
                                 const float* __restrict__ beta)
{
    const int bg = blockIdx.x;
    const int b  = bg >> 3;
    const int g  = bg & 7;
    const int t  = threadIdx.x;         // 256 threads

    const long base = ((long)b * HW) * C + g * CG;

    __shared__ float s_sum[256];
    __shared__ float s_sq [256];

    float lsum = 0.f, lsq = 0.f;
    for (int idx = t; idx < HW * CG; idx += 256) {
        int n = idx >> 6;
        int c = idx & 63;
        float v = x[base + (long)n * C + c];
        lsum += v;
        lsq  += v * v;
    }
    s_sum[t] = lsum; s_sq[t] = lsq;
    __syncthreads();
    for (int s = 128; s > 0; s >>= 1) {
        if (t < s) { s_sum[t] += s_sum[t + s]; s_sq[t] += s_sq[t + s]; }
        __syncthreads();
    }
    const float inv_n = 1.0f / (HW * CG);
    const float mean  = s_sum[0] * inv_n;
    const float var   = s_sq[0] * inv_n - mean * mean;
    const float rstd  = rsqrtf(var + EPS);

    for (int idx = t; idx < HW * CG; idx += 256) {
        int n = idx >> 6;
        int c = idx & 63;
        int gc = g * CG + c;
        float v = x[base + (long)n * C + c];
        g_h[base + (long)n * C + c] = (v - mean) * rstd * gamma[gc] + beta[gc];
    }
}

// ---------------------------------------------------------------------------
// TF32 tensor-core GEMM core.
// Block tile 128x128, BK=32, 256 threads = 8 warps (2 x 4), warp tile 64x32.
// mma.sync.m16n8k8 tf32. Smem layout: As[128][33], Bs[128][33] (tf32 bits,
// rows = non-K dim, +1 pad). NN-case B ([K][N] row-major) is transposed
// during the copy so fragment reads are identical for both cases.
// TRANS_COPY=false: B is [N][K] row-major (NT gemm, direct copy)
// TRANS_COPY=true : B is [K][N] row-major (NN gemm, transpose on copy)
// ---------------------------------------------------------------------------
__device__ __forceinline__ unsigned f2tf(float f) {
    unsigned u;
    asm("cvt.rna.tf32.f32 %0, %1;" : "=r"(u) : "f"(f));
    return u;
}

__device__ __forceinline__ void mma_tf32(float c[4],
                                         unsigned a0, unsigned a1, unsigned a2, unsigned a3,
                                         unsigned b0, unsigned b1)
{
    asm("mma.sync.aligned.m16n8k8.row.col.f32.tf32.tf32.f32 "
        "{%0,%1,%2,%3},{%4,%5,%6,%7},{%8,%9},{%0,%1,%2,%3};"
        : "+f"(c[0]), "+f"(c[1]), "+f"(c[2]), "+f"(c[3])
        : "r"(a0), "r"(a1), "r"(a2), "r"(a3), "r"(b0), "r"(b1));
}

constexpr int BKQ = 32;   // k tile
constexpr int SLD = 33;   // smem row stride (pad)

template<bool TRANS_COPY>
__device__ __forceinline__ void gemm_mma_core(const float* __restrict__ A,
                                              const float* __restrict__ B,
                                              int K, int lda, int ldb,
                                              float acc[4][4][4])
{
    __shared__ unsigned As[128 * SLD];
    __shared__ unsigned Bs[128 * SLD];

    const int tid  = threadIdx.x;
    const int lane = tid & 31;
    const int warp = tid >> 5;
    const int wm   = warp >> 2;        // 0..1
    const int wn   = warp & 3;         // 0..3
    const int lq   = lane >> 2;        // 0..7
    const int lr   = lane & 3;         // 0..3

    for (int k0 = 0; k0 < K; k0 += BKQ) {
        // --- copy A tile: 128 rows x 32 k, float4 along K ---
        #pragma unroll
        for (int it = 0; it < 4; it++) {
            int idx  = it * 256 + tid;          // 0..1023
            int row  = idx >> 3;                // 0..127
            int col4 = (idx & 7) * 4;           // 0,4,..,28
            float4 v = *reinterpret_cast<const float4*>(&A[(long)row * lda + k0 + col4]);
            unsigned* s = &As[row * SLD + col4];
            s[0] = f2tf(v.x); s[1] = f2tf(v.y); s[2] = f2tf(v.z); s[3] = f2tf(v.w);
        }
        // --- copy B tile ---
        if (TRANS_COPY) {
            // B is [K][N]: tile 32 k-rows x 128 n-cols, transpose into Bs[n][k]
            #pragma unroll
            for (int it = 0; it < 4; it++) {
                int idx  = it * 256 + tid;      // 0..1023
                int kr   = idx >> 5;            // 0..31
                int col4 = (idx & 31) * 4;      // 0..124
                float4 v = *reinterpret_cast<const float4*>(&B[(long)(k0 + kr) * ldb + col4]);
                Bs[(col4 + 0) * SLD + kr] = f2tf(v.x);
                Bs[(col4 + 1) * SLD + kr] = f2tf(v.y);
                Bs[(col4 + 2) * SLD + kr] = f2tf(v.z);
                Bs[(col4 + 3) * SLD + kr] = f2tf(v.w);
            }
        } else {
            // B is [N][K]: same shape as A
            #pragma unroll
            for (int it = 0; it < 4; it++) {
                int idx  = it * 256 + tid;
                int row  = idx >> 3;
                int col4 = (idx & 7) * 4;
                float4 v = *reinterpret_cast<const float4*>(&B[(long)row * ldb + k0 + col4]);
                unsigned* s = &Bs[row * SLD + col4];
                s[0] = f2tf(v.x); s[1] = f2tf(v.y); s[2] = f2tf(v.z); s[3] = f2tf(v.w);
            }
        }
        __syncthreads();

        // --- 4 k-substeps of 8 ---
        #pragma unroll
        for (int kk = 0; kk < 4; kk++) {
            const int kb = kk * 8;
            unsigned af[4][4], bf[4][2];
            #pragma unroll
            for (int mf = 0; mf < 4; mf++) {
                const unsigned* ap = &As[(wm * 64 + mf * 16 + lq) * SLD + kb + lr];
                af[mf][0] = ap[0];
                af[mf][1] = ap[8 * SLD];
                af[mf][2] = ap[4];
                af[mf][3] = ap[8 * SLD + 4];
            }
            #pragma unroll
            for (int nf = 0; nf < 4; nf++) {
                const unsigned* bp = &Bs[(wn * 32 + nf * 8 + lq) * SLD + kb + lr];
                bf[nf][0] = bp[0];
                bf[nf][1] = bp[4];
            }
            #pragma unroll
            for (int mf = 0; mf < 4; mf++)
                #pragma unroll
                for (int nf = 0; nf < 4; nf++)
                    mma_tf32(acc[mf][nf], af[mf][0], af[mf][1], af[mf][2], af[mf][3],
                             bf[nf][0], bf[nf][1]);
        }
        __syncthreads();
    }
}

// Epilogue coordinate helpers: for frag (mf,nf), thread lane:
//   row = wm*64 + mf*16 + lane/4 (+8 for c2/c3)
//   col = wn*32 + nf*8 + 2*(lane%4) (+1 for c1/c3)

// ---------------------------------------------------------------------------
// QKV GEMM: [NTOK,512] x [512,1536] + bias -> g_q/g_k/g_v
// ---------------------------------------------------------------------------
__global__ __launch_bounds__(256) void qkv_gemm_kernel(const float* __restrict__ w,
                                                       const float* __restrict__ bias)
{
    const int n0 = blockIdx.x * 128;
    const int m0 = blockIdx.y * 128;
    float acc[4][4][4] = {};
    gemm_mma_core<true>(g_h + (long)m0 * C, w + n0, C, C, QKVN, acc);

    const int lane = threadIdx.x & 31, warp = threadIdx.x >> 5;
    const int wm = warp >> 2, wn = warp & 3;
    const int which = n0 >> 9;   // 0=q 1=k 2=v
    float* dst = (which == 0) ? g_q : (which == 1) ? g_k : g_v;
    #pragma unroll
    for (int mf = 0; mf < 4; mf++) {
        const int r0 = m0 + wm * 64 + mf * 16 + (lane >> 2);
        #pragma unroll
        for (int nf = 0; nf < 4; nf++) {
            const int n = n0 + wn * 32 + nf * 8 + 2 * (lane & 3);
            const int c = n & 511;
            float b0 = bias[n], b1 = bias[n + 1];
            *reinterpret_cast<float2*>(&dst[(long)r0 * C + c]) =
                make_float2(acc[mf][nf][0] + b0, acc[mf][nf][1] + b1);
            *reinterpret_cast<float2*>(&dst[(long)(r0 + 8) * C + c]) =
                make_float2(acc[mf][nf][2] + b0, acc[mf][nf][3] + b1);
        }
    }
}

// ---------------------------------------------------------------------------
// scores[b,m,n] = scale * q[b,m,:] . k[b,n,:]   (NT)
// ---------------------------------------------------------------------------
__global__ __launch_bounds__(256) void scores_kernel()
{
    const int b  = blockIdx.z;
    const int n0 = blockIdx.x * 128;
    const int m0 = blockIdx.y * 128;
    const float scale = rsqrtf((float)C);

    float acc[4][4][4] = {};
    gemm_mma_core<false>(g_q + (long)b * HW * C + (long)m0 * C,
                         g_k + (long)b * HW * C + (long)n0 * C, C, C, C, acc);

    float* out = g_scores + (long)b * HW * HW;
    const int lane = threadIdx.x & 31, warp = threadIdx.x >> 5;
    const int wm = warp >> 2, wn = warp & 3;
    #pragma unroll
    for (int mf = 0; mf < 4; mf++) {
        const int r0 = m0 + wm * 64 + mf * 16 + (lane >> 2);
        #pragma unroll
        for (int nf = 0; nf < 4; nf++) {
            const int n = n0 + wn * 32 + nf * 8 + 2 * (lane & 3);
            *reinterpret_cast<float2*>(&out[(long)r0 * HW + n]) =
                make_float2(acc[mf][nf][0] * scale, acc[mf][nf][1] * scale);
            *reinterpret_cast<float2*>(&out[(long)(r0 + 8) * HW + n]) =
                make_float2(acc[mf][nf][2] * scale, acc[mf][nf][3] * scale);
        }
    }
}

// ---------------------------------------------------------------------------
// Row softmax over 1024 entries.
// ---------------------------------------------------------------------------
__global__ void softmax_kernel()
{
    __shared__ float red[256];
    float* p = g_scores + (long)blockIdx.x * HW;
    const int t = threadIdx.x;

    float v0 = p[t], v1 = p[t + 256], v2 = p[t + 512], v3 = p[t + 768];
    float mx = fmaxf(fmaxf(v0, v1), fmaxf(v2, v3));
    red[t] = mx; __syncthreads();
    for (int s = 128; s > 0; s >>= 1) {
        if (t < s) red[t] = fmaxf(red[t], red[t + s]);
        __syncthreads();
    }
    mx = red[0];
    __syncthreads();

    v0 = __expf(v0 - mx); v1 = __expf(v1 - mx);
    v2 = __expf(v2 - mx); v3 = __expf(v3 - mx);
    red[t] = v0 + v1 + v2 + v3; __syncthreads();
    for (int s = 128; s > 0; s >>= 1) {
        if (t < s) red[t] += red[t + s];
        __syncthreads();
    }
    const float inv = 1.0f / red[0];
    p[t]       = v0 * inv;
    p[t + 256] = v1 * inv;
    p[t + 512] = v2 * inv;
    p[t + 768] = v3 * inv;
}

// ---------------------------------------------------------------------------
// attention output: g_h[b,m,c] = sum_n attn[b,m,n] * v[b,n,c]  (NN)
// ---------------------------------------------------------------------------
__global__ __launch_bounds__(256) void av_kernel()
{
    const int b  = blockIdx.z;
    const int n0 = blockIdx.x * 128;   // channel tile
    const int m0 = blockIdx.y * 128;   // query tile

    float acc[4][4][4] = {};
    gemm_mma_core<true>(g_scores + (long)b * HW * HW + (long)m0 * HW,
                        g_v + (long)b * HW * C + n0, HW, HW, C, acc);

    float* out = g_h + (long)b * HW * C;
    const int lane = threadIdx.x & 31, warp = threadIdx.x >> 5;
    const int wm = warp >> 2, wn = warp & 3;
    #pragma unroll
    for (int mf = 0; mf < 4; mf++) {
        const int r0 = m0 + wm * 64 + mf * 16 + (lane >> 2);
        #pragma unroll
        for (int nf = 0; nf < 4; nf++) {
            const int n = n0 + wn * 32 + nf * 8 + 2 * (lane & 3);
            *reinterpret_cast<float2*>(&out[(long)r0 * C + n]) =
                make_float2(acc[mf][nf][0], acc[mf][nf][1]);
            *reinterpret_cast<float2*>(&out[(long)(r0 + 8) * C + n]) =
                make_float2(acc[mf][nf][2], acc[mf][nf][3]);
        }
    }
}

// ---------------------------------------------------------------------------
// proj + bias + residual: out = x + g_h @ w_proj + b_proj
// ---------------------------------------------------------------------------
__global__ __launch_bounds__(256) void proj_kernel(const float* __restrict__ x,
                                                   const float* __restrict__ w,
                                                   const float* __restrict__ bias,
                                                   float* __restrict__ out)
{
    const int n0 = blockIdx.x * 128;
    const int m0 = blockIdx.y * 128;
    float acc[4][4][4] = {};
    gemm_mma_core<true>(g_h + (long)m0 * C, w + n0, C, C, C, acc);

    const int lane = threadIdx.x & 31, warp = threadIdx.x >> 5;
    const int wm = warp >> 2, wn = warp & 3;
    #pragma unroll
    for (int mf = 0; mf < 4; mf++) {
        const int r0 = m0 + wm * 64 + mf * 16 + (lane >> 2);
        #pragma unroll
        for (int nf = 0; nf < 4; nf++) {
            const int n = n0 + wn * 32 + nf * 8 + 2 * (lane & 3);
            float b0 = bias[n], b1 = bias[n + 1];
            float2 x0 = *reinterpret_cast<const float2*>(&x[(long)r0 * C + n]);
            float2 x1 = *reinterpret_cast<const float2*>(&x[(long)(r0 + 8) * C + n]);
            *reinterpret_cast<float2*>(&out[(long)r0 * C + n]) =
                make_float2(acc[mf][nf][0] + b0 + x0.x, acc[mf][nf][1] + b1 + x0.y);
            *reinterpret_cast<float2*>(&out[(long)(r0 + 8) * C + n]) =
                make_float2(acc[mf][nf][2] + b0 + x1.x, acc[mf][nf][3] + b1 + x1.y);
        }
    }
}

// ---------------------------------------------------------------------------
extern "C" void kernel_launch(void* const* d_in, const int* in_sizes, int n_in,
                              void* d_out, int out_size)
{
    const float* x      = (const float*)d_in[0];
    const float* gamma  = (const float*)d_in[1];
    const float* beta   = (const float*)d_in[2];
    const float* w_qkv  = (const float*)d_in[3];
    const float* b_qkv  = (const float*)d_in[4];
    const float* w_proj = (const float*)d_in[5];
    const float* b_proj = (const float*)d_in[6];
    float* out = (float*)d_out;

    groupnorm_kernel<<<Bb * G, 256>>>(x, gamma, beta);
    qkv_gemm_kernel<<<dim3(QKVN / 128, NTOK / 128), 256>>>(w_qkv, b_qkv);
    scores_kernel<<<dim3(HW / 128, HW / 128, Bb), 256>>>();
    softmax_kernel<<<Bb * HW, 256>>>();
    av_kernel<<<dim3(C / 128, HW / 128, Bb), 256>>>();
    proj_kernel<<<dim3(C / 128, NTOK / 128), 256>>>(x, w_proj, b_proj, out);
}

// round 6
// speedup vs baseline: 3.7659x; 2.2645x over previous
#include <cuda_runtime.h>
#include <cuda_bf16.h>
#include <math.h>

// Problem constants
constexpr int Bb   = 32;          // batch
constexpr int HW   = 1024;        // H*W tokens per batch
constexpr int C    = 512;         // channels
constexpr int G    = 8;           // groups
constexpr int CG   = C / G;       // 64 channels per group
constexpr int NTOK = Bb * HW;     // 32768 total tokens
constexpr int QKVN = 3 * C;       // 1536
constexpr float EPS = 1e-3f;

// Scratch (device globals -> allowed; no allocations). 384 MB total.
__device__ float g_h [ (long)NTOK * C ];           // 64 MB (normed in, then attn out)
__device__ float g_q [ (long)NTOK * C ];           // 64 MB
__device__ float g_k [ (long)NTOK * C ];           // 64 MB
__device__ float g_v [ (long)NTOK * C ];           // 64 MB
__device__ float g_scores[ (long)Bb * HW * HW ];   // 128 MB

// ---------------------------------------------------------------------------
// GroupNorm
// ---------------------------------------------------------------------------
__global__ void groupnorm_kernel(const float* __restrict__ x,
                                 const float* __restrict__ gamma,
                                 const float* __restrict__ beta)
{
    const int bg = blockIdx.x;
    const int b  = bg >> 3;
    const int g  = bg & 7;
    const int t  = threadIdx.x;         // 256 threads

    const long base = ((long)b * HW) * C + g * CG;

    __shared__ float s_sum[256];
    __shared__ float s_sq [256];

    float lsum = 0.f, lsq = 0.f;
    for (int idx = t; idx < HW * CG; idx += 256) {
        int n = idx >> 6;
        int c = idx & 63;
        float v = x[base + (long)n * C + c];
        lsum += v;
        lsq  += v * v;
    }
    s_sum[t] = lsum; s_sq[t] = lsq;
    __syncthreads();
    for (int s = 128; s > 0; s >>= 1) {
        if (t < s) { s_sum[t] += s_sum[t + s]; s_sq[t] += s_sq[t + s]; }
        __syncthreads();
    }
    const float inv_n = 1.0f / (HW * CG);
    const float mean  = s_sum[0] * inv_n;
    const float var   = s_sq[0] * inv_n - mean * mean;
    const float rstd  = rsqrtf(var + EPS);

    for (int idx = t; idx < HW * CG; idx += 256) {
        int n = idx >> 6;
        int c = idx & 63;
        int gc = g * CG + c;
        float v = x[base + (long)n * C + c];
        g_h[base + (long)n * C + c] = (v - mean) * rstd * gamma[gc] + beta[gc];
    }
}

// ---------------------------------------------------------------------------
// TF32 tensor-core GEMM core, cp.async double-buffered.
// Block tile 128x128, BK=32, 256 threads = 8 warps (2x4), warp tile 64x32.
// Raw fp32 bits are fed to mma.tf32 (HW truncates mantissa).
// Smem: As[2][128][36]  (rows = M, cols = K, stride 36 => conflict-free frags)
//       NT-B (B=[N][K]): Bs[2][128][36] like A
//       NN-B (B=[K][N]): Bs[2][32][136] k-major (no transpose needed)
// ---------------------------------------------------------------------------
constexpr int BK   = 32;
constexpr int SLDA = 36;    // A / NT-B smem row stride (words)
constexpr int SLDB = 136;   // NN-B smem row stride (words)

constexpr int A_WORDS_BUF  = 128 * SLDA;          // 4608
constexpr int BNT_WORDS_BUF= 128 * SLDA;          // 4608
constexpr int BNN_WORDS_BUF= BK * SLDB;           // 4352
constexpr int SMEM_BYTES_NT = (2*A_WORDS_BUF + 2*BNT_WORDS_BUF) * 4;  // 73728
constexpr int SMEM_BYTES_NN = (2*A_WORDS_BUF + 2*BNN_WORDS_BUF) * 4;  // 71680

__device__ __forceinline__ void cp16(unsigned* dst_smem, const float* src) {
    unsigned s = (unsigned)__cvta_generic_to_shared(dst_smem);
    asm volatile("cp.async.cg.shared.global [%0], [%1], 16;" :: "r"(s), "l"(src));
}
__device__ __forceinline__ void cp_commit() {
    asm volatile("cp.async.commit_group;");
}
template<int N>
__device__ __forceinline__ void cp_wait() {
    asm volatile("cp.async.wait_group %0;" :: "n"(N));
}

__device__ __forceinline__ void mma_tf32(float c[4],
                                         unsigned a0, unsigned a1, unsigned a2, unsigned a3,
                                         unsigned b0, unsigned b1)
{
    asm("mma.sync.aligned.m16n8k8.row.col.f32.tf32.tf32.f32 "
        "{%0,%1,%2,%3},{%4,%5,%6,%7},{%8,%9},{%0,%1,%2,%3};"
        : "+f"(c[0]), "+f"(c[1]), "+f"(c[2]), "+f"(c[3])
        : "r"(a0), "r"(a1), "r"(a2), "r"(a3), "r"(b0), "r"(b1));
}

// TRANS_B=true : B is [K][N] row-major (NN gemm)
// TRANS_B=false: B is [N][K] row-major (NT gemm)
template<bool TRANS_B>
__device__ __forceinline__ void gemm_mma_core(const float* __restrict__ A,
                                              const float* __restrict__ B,
                                              int K, int lda, int ldb,
                                              float acc[4][4][4])
{
    extern __shared__ unsigned dynsmem[];
    unsigned* As = dynsmem;                          // 2 bufs
    unsigned* Bs = dynsmem + 2 * A_WORDS_BUF;        // 2 bufs

    const int tid  = threadIdx.x;
    const int lane = tid & 31;
    const int warp = tid >> 5;
    const int wm   = warp >> 2;        // 0..1
    const int wn   = warp & 3;         // 0..3
    const int lq   = lane >> 2;        // 0..7
    const int lr   = lane & 3;         // 0..3

    // ---- tile copy (cp.async, 16B chunks) ----
    auto copy_tiles = [&](int k0, int buf) {
        unsigned* as = As + buf * A_WORDS_BUF;
        // A: 128 rows x 32 k = 1024 chunks of 16B -> 4 per thread
        #pragma unroll
        for (int it = 0; it < 4; it++) {
            int idx  = it * 256 + tid;
            int row  = idx >> 3;
            int col4 = (idx & 7) * 4;
            cp16(&as[row * SLDA + col4], &A[(long)row * lda + k0 + col4]);
        }
        if (TRANS_B) {
            // B[K][N]: 32 k-rows x 128 n = 4096 words = 1024 chunks -> 4/thread
            unsigned* bs = Bs + buf * BNN_WORDS_BUF;
            #pragma unroll
            for (int it = 0; it < 4; it++) {
                int idx = it * 256 + tid;       // 0..1023
                int kr  = idx >> 5;             // 0..31
                int n4  = (idx & 31) * 4;       // 0..124
                cp16(&bs[kr * SLDB + n4], &B[(long)(k0 + kr) * ldb + n4]);
            }
        } else {
            // B[N][K]: same shape as A
            unsigned* bs = Bs + buf * BNT_WORDS_BUF;
            #pragma unroll
            for (int it = 0; it < 4; it++) {
                int idx  = it * 256 + tid;
                int row  = idx >> 3;
                int col4 = (idx & 7) * 4;
                cp16(&bs[row * SLDA + col4], &B[(long)row * ldb + k0 + col4]);
            }
        }
    };

    // ---- compute one staged tile ----
    auto compute_tile = [&](int buf) {
        const unsigned* as = As + buf * A_WORDS_BUF;
        const unsigned* bs = Bs + buf * (TRANS_B ? BNN_WORDS_BUF : BNT_WORDS_BUF);
        #pragma unroll
        for (int kk = 0; kk < 4; kk++) {
            const int kb = kk * 8;
            unsigned af[4][4], bf[4][2];
            #pragma unroll
            for (int mf = 0; mf < 4; mf++) {
                const unsigned* ap = &as[(wm * 64 + mf * 16 + lq) * SLDA + kb + lr];
                af[mf][0] = ap[0];
                af[mf][1] = ap[8 * SLDA];
                af[mf][2] = ap[4];
                af[mf][3] = ap[8 * SLDA + 4];
            }
            #pragma unroll
            for (int nf = 0; nf < 4; nf++) {
                const int nn = wn * 32 + nf * 8 + lq;
                if (TRANS_B) {
                    bf[nf][0] = bs[(kb + lr)     * SLDB + nn];
                    bf[nf][1] = bs[(kb + lr + 4) * SLDB + nn];
                } else {
                    bf[nf][0] = bs[nn * SLDA + kb + lr];
                    bf[nf][1] = bs[nn * SLDA + kb + lr + 4];
                }
            }
            #pragma unroll
            for (int mf = 0; mf < 4; mf++)
                #pragma unroll
                for (int nf = 0; nf < 4; nf++)
                    mma_tf32(acc[mf][nf], af[mf][0], af[mf][1], af[mf][2], af[mf][3],
                             bf[nf][0], bf[nf][1]);
        }
    };

    const int nit = K / BK;
    copy_tiles(0, 0);
    cp_commit();
    for (int it = 0; it < nit; it++) {
        const int buf = it & 1;
        if (it + 1 < nit) {
            copy_tiles((it + 1) * BK, buf ^ 1);
            cp_commit();
            cp_wait<1>();
        } else {
            cp_wait<0>();
        }
        __syncthreads();
        compute_tile(buf);
        __syncthreads();
    }
}

// Epilogue coords: frag (mf,nf), lane: row = wm*64+mf*16+lane/4 (+8 for c2/c3),
//                  col = wn*32+nf*8+2*(lane%4) (+1 for c1/c3)

// ---------------------------------------------------------------------------
// QKV GEMM: [NTOK,512] x [512,1536] + bias -> g_q/g_k/g_v
// ---------------------------------------------------------------------------
__global__ __launch_bounds__(256) void qkv_gemm_kernel(const float* __restrict__ w,
                                                       const float* __restrict__ bias)
{
    const int n0 = blockIdx.x * 128;
    const int m0 = blockIdx.y * 128;
    float acc[4][4][4] = {};
    gemm_mma_core<true>(g_h + (long)m0 * C, w + n0, C, C, QKVN, acc);

    const int lane = threadIdx.x & 31, warp = threadIdx.x >> 5;
    const int wm = warp >> 2, wn = warp & 3;
    const int which = n0 >> 9;   // 0=q 1=k 2=v
    float* dst = (which == 0) ? g_q : (which == 1) ? g_k : g_v;
    #pragma unroll
    for (int mf = 0; mf < 4; mf++) {
        const int r0 = m0 + wm * 64 + mf * 16 + (lane >> 2);
        #pragma unroll
        for (int nf = 0; nf < 4; nf++) {
            const int n = n0 + wn * 32 + nf * 8 + 2 * (lane & 3);
            const int c = n & 511;
            float b0 = bias[n], b1 = bias[n + 1];
            *reinterpret_cast<float2*>(&dst[(long)r0 * C + c]) =
                make_float2(acc[mf][nf][0] + b0, acc[mf][nf][1] + b1);
            *reinterpret_cast<float2*>(&dst[(long)(r0 + 8) * C + c]) =
                make_float2(acc[mf][nf][2] + b0, acc[mf][nf][3] + b1);
        }
    }
}

// ---------------------------------------------------------------------------
// scores[b,m,n] = scale * q[b,m,:] . k[b,n,:]   (NT)
// ---------------------------------------------------------------------------
__global__ __launch_bounds__(256) void scores_kernel()
{
    const int b  = blockIdx.z;
    const int n0 = blockIdx.x * 128;
    const int m0 = blockIdx.y * 128;
    const float scale = rsqrtf((float)C);

    float acc[4][4][4] = {};
    gemm_mma_core<false>(g_q + (long)b * HW * C + (long)m0 * C,
                         g_k + (long)b * HW * C + (long)n0 * C, C, C, C, acc);

    float* out = g_scores + (long)b * HW * HW;
    const int lane = threadIdx.x & 31, warp = threadIdx.x >> 5;
    const int wm = warp >> 2, wn = warp & 3;
    #pragma unroll
    for (int mf = 0; mf < 4; mf++) {
        const int r0 = m0 + wm * 64 + mf * 16 + (lane >> 2);
        #pragma unroll
        for (int nf = 0; nf < 4; nf++) {
            const int n = n0 + wn * 32 + nf * 8 + 2 * (lane & 3);
            *reinterpret_cast<float2*>(&out[(long)r0 * HW + n]) =
                make_float2(acc[mf][nf][0] * scale, acc[mf][nf][1] * scale);
            *reinterpret_cast<float2*>(&out[(long)(r0 + 8) * HW + n]) =
                make_float2(acc[mf][nf][2] * scale, acc[mf][nf][3] * scale);
        }
    }
}

// ---------------------------------------------------------------------------
// Row softmax over 1024 entries: 256 threads, float4 + shuffle reductions.
// ---------------------------------------------------------------------------
__global__ void softmax_kernel()
{
    __shared__ float wred[8];
    float4* p = reinterpret_cast<float4*>(g_scores + (long)blockIdx.x * HW);
    const int t    = threadIdx.x;
    const int lane = t & 31;
    const int warp = t >> 5;

    float4 v = p[t];
    float mx = fmaxf(fmaxf(v.x, v.y), fmaxf(v.z, v.w));
    #pragma unroll
    for (int o = 16; o > 0; o >>= 1)
        mx = fmaxf(mx, __shfl_xor_sync(0xffffffffu, mx, o));
    if (lane == 0) wred[warp] = mx;
    __syncthreads();
    mx = wred[0];
    #pragma unroll
    for (int i = 1; i < 8; i++) mx = fmaxf(mx, wred[i]);
    __syncthreads();

    v.x = __expf(v.x - mx); v.y = __expf(v.y - mx);
    v.z = __expf(v.z - mx); v.w = __expf(v.w - mx);
    float s = v.x + v.y + v.z + v.w;
    #pragma unroll
    for (int o = 16; o > 0; o >>= 1)
        s += __shfl_xor_sync(0xffffffffu, s, o);
    if (lane == 0) wred[warp] = s;
    __syncthreads();
    s = wred[0];
    #pragma unroll
    for (int i = 1; i < 8; i++) s += wred[i];

    const float inv = 1.0f / s;
    v.x *= inv; v.y *= inv; v.z *= inv; v.w *= inv;
    p[t] = v;
}

// ---------------------------------------------------------------------------
// attention output: g_h[b,m,c] = sum_n attn[b,m,n] * v[b,n,c]  (NN)
// ---------------------------------------------------------------------------
__global__ __launch_bounds__(256) void av_kernel()
{
    const int b  = blockIdx.z;
    const int n0 = blockIdx.x * 128;   // channel tile
    const int m0 = blockIdx.y * 128;   // query tile

    float acc[4][4][4] = {};
    gemm_mma_core<true>(g_scores + (long)b * HW * HW + (long)m0 * HW,
                        g_v + (long)b * HW * C + n0, HW, HW, C, acc);

    float* out = g_h + (long)b * HW * C;
    const int lane = threadIdx.x & 31, warp = threadIdx.x >> 5;
    const int wm = warp >> 2, wn = warp & 3;
    #pragma unroll
    for (int mf = 0; mf < 4; mf++) {
        const int r0 = m0 + wm * 64 + mf * 16 + (lane >> 2);
        #pragma unroll
        for (int nf = 0; nf < 4; nf++) {
            const int n = n0 + wn * 32 + nf * 8 + 2 * (lane & 3);
            *reinterpret_cast<float2*>(&out[(long)r0 * C + n]) =
                make_float2(acc[mf][nf][0], acc[mf][nf][1]);
            *reinterpret_cast<float2*>(&out[(long)(r0 + 8) * C + n]) =
                make_float2(acc[mf][nf][2], acc[mf][nf][3]);
        }
    }
}

// ---------------------------------------------------------------------------
// proj + bias + residual: out = x + g_h @ w_proj + b_proj
// ---------------------------------------------------------------------------
__global__ __launch_bounds__(256) void proj_kernel(const float* __restrict__ x,
                                                   const float* __restrict__ w,
                                                   const float* __restrict__ bias,
                                                   float* __restrict__ out)
{
    const int n0 = blockIdx.x * 128;
    const int m0 = blockIdx.y * 128;
    float acc[4][4][4] = {};
    gemm_mma_core<true>(g_h + (long)m0 * C, w + n0, C, C, C, acc);

    const int lane = threadIdx.x & 31, warp = threadIdx.x >> 5;
    const int wm = warp >> 2, wn = warp & 3;
    #pragma unroll
    for (int mf = 0; mf < 4; mf++) {
        const int r0 = m0 + wm * 64 + mf * 16 + (lane >> 2);
        #pragma unroll
        for (int nf = 0; nf < 4; nf++) {
            const int n = n0 + wn * 32 + nf * 8 + 2 * (lane & 3);
            float b0 = bias[n], b1 = bias[n + 1];
            float2 x0 = *reinterpret_cast<const float2*>(&x[(long)r0 * C + n]);
            float2 x1 = *reinterpret_cast<const float2*>(&x[(long)(r0 + 8) * C + n]);
            *reinterpret_cast<float2*>(&out[(long)r0 * C + n]) =
                make_float2(acc[mf][nf][0] + b0 + x0.x, acc[mf][nf][1] + b1 + x0.y);
            *reinterpret_cast<float2*>(&out[(long)(r0 + 8) * C + n]) =
                make_float2(acc[mf][nf][2] + b0 + x1.x, acc[mf][nf][3] + b1 + x1.y);
        }
    }
}

// ---------------------------------------------------------------------------
extern "C" void kernel_launch(void* const* d_in, const int* in_sizes, int n_in,
                              void* d_out, int out_size)
{
    const float* x      = (const float*)d_in[0];
    const float* gamma  = (const float*)d_in[1];
    const float* beta   = (const float*)d_in[2];
    const float* w_qkv  = (const float*)d_in[3];
    const float* b_qkv  = (const float*)d_in[4];
    const float* w_proj = (const float*)d_in[5];
    const float* b_proj = (const float*)d_in[6];
    float* out = (float*)d_out;

    // Opt-in to >48KB dynamic smem (idempotent, capture-safe, no allocation).
    cudaFuncSetAttribute(qkv_gemm_kernel, cudaFuncAttributeMaxDynamicSharedMemorySize, SMEM_BYTES_NN);
    cudaFuncSetAttribute(scores_kernel,   cudaFuncAttributeMaxDynamicSharedMemorySize, SMEM_BYTES_NT);
    cudaFuncSetAttribute(av_kernel,       cudaFuncAttributeMaxDynamicSharedMemorySize, SMEM_BYTES_NN);
    cudaFuncSetAttribute(proj_kernel,     cudaFuncAttributeMaxDynamicSharedMemorySize, SMEM_BYTES_NN);

    groupnorm_kernel<<<Bb * G, 256>>>(x, gamma, beta);
    qkv_gemm_kernel<<<dim3(QKVN / 128, NTOK / 128), 256, SMEM_BYTES_NN>>>(w_qkv, b_qkv);
    scores_kernel<<<dim3(HW / 128, HW / 128, Bb), 256, SMEM_BYTES_NT>>>();
    softmax_kernel<<<Bb * HW, 256>>>();
    av_kernel<<<dim3(C / 128, HW / 128, Bb), 256, SMEM_BYTES_NN>>>();
    proj_kernel<<<dim3(C / 128, NTOK / 128), 256, SMEM_BYTES_NN>>>(x, w_proj, b_proj, out);
}

// round 7
// speedup vs baseline: 3.7700x; 1.0011x over previous
#include <cuda_runtime.h>
#include <cuda_bf16.h>
#include <math.h>

// Problem constants
constexpr int Bb   = 32;          // batch
constexpr int HW   = 1024;        // H*W tokens per batch
constexpr int C    = 512;         // channels
constexpr int G    = 8;           // groups
constexpr int CG   = C / G;       // 64 channels per group
constexpr int NTOK = Bb * HW;     // 32768 total tokens
constexpr int QKVN = 3 * C;       // 1536
constexpr float EPS = 1e-3f;

// Scratch (device globals -> allowed; no allocations). 384 MB total.
__device__ float g_h [ (long)NTOK * C ];           // 64 MB (normed in, then attn out)
__device__ float g_q [ (long)NTOK * C ];           // 64 MB
__device__ float g_k [ (long)NTOK * C ];           // 64 MB
__device__ float g_v [ (long)NTOK * C ];           // 64 MB
__device__ float g_scores[ (long)Bb * HW * HW ];   // 128 MB

// ---------------------------------------------------------------------------
// GroupNorm
// ---------------------------------------------------------------------------
__global__ void groupnorm_kernel(const float* __restrict__ x,
                                 const float* __restrict__ gamma,
                                 const float* __restrict__ beta)
{
    const int bg = blockIdx.x;
    const int b  = bg >> 3;
    const int g  = bg & 7;
    const int t  = threadIdx.x;         // 256 threads

    const long base = ((long)b * HW) * C + g * CG;

    __shared__ float s_sum[256];
    __shared__ float s_sq [256];

    float lsum = 0.f, lsq = 0.f;
    for (int idx = t; idx < HW * CG; idx += 256) {
        int n = idx >> 6;
        int c = idx & 63;
        float v = x[base + (long)n * C + c];
        lsum += v;
        lsq  += v * v;
    }
    s_sum[t] = lsum; s_sq[t] = lsq;
    __syncthreads();
    for (int s = 128; s > 0; s >>= 1) {
        if (t < s) { s_sum[t] += s_sum[t + s]; s_sq[t] += s_sq[t + s]; }
        __syncthreads();
    }
    const float inv_n = 1.0f / (HW * CG);
    const float mean  = s_sum[0] * inv_n;
    const float var   = s_sq[0] * inv_n - mean * mean;
    const float rstd  = rsqrtf(var + EPS);

    for (int idx = t; idx < HW * CG; idx += 256) {
        int n = idx >> 6;
        int c = idx & 63;
        int gc = g * CG + c;
        float v = x[base + (long)n * C + c];
        g_h[base + (long)n * C + c] = (v - mean) * rstd * gamma[gc] + beta[gc];
    }
}

// ---------------------------------------------------------------------------
// TF32 tensor-core GEMM core, cp.async double-buffered.
// Block tile 128x128, BK=32, 256 threads = 8 warps (2x4), warp tile 64x32.
// Raw fp32 bits are fed to mma.tf32 (HW truncates mantissa).
// Smem: As[2][128][36]  (rows = M, cols = K, stride 36 => conflict-free frags)
//       NT-B (B=[N][K]): Bs[2][128][36] like A
//       NN-B (B=[K][N]): Bs[2][32][136] k-major (no transpose needed)
// ---------------------------------------------------------------------------
constexpr int BK   = 32;
constexpr int SLDA = 36;    // A / NT-B smem row stride (words)
constexpr int SLDB = 136;   // NN-B smem row stride (words)

constexpr int A_WORDS_BUF  = 128 * SLDA;          // 4608
constexpr int BNT_WORDS_BUF= 128 * SLDA;          // 4608
constexpr int BNN_WORDS_BUF= BK * SLDB;           // 4352
constexpr int SMEM_BYTES_NT = (2*A_WORDS_BUF + 2*BNT_WORDS_BUF) * 4;  // 73728
constexpr int SMEM_BYTES_NN = (2*A_WORDS_BUF + 2*BNN_WORDS_BUF) * 4;  // 71680

__device__ __forceinline__ void cp16(unsigned* dst_smem, const float* src) {
    unsigned s = (unsigned)__cvta_generic_to_shared(dst_smem);
    asm volatile("cp.async.cg.shared.global [%0], [%1], 16;" :: "r"(s), "l"(src));
}
__device__ __forceinline__ void cp_commit() {
    asm volatile("cp.async.commit_group;");
}
template<int N>
__device__ __forceinline__ void cp_wait() {
    asm volatile("cp.async.wait_group %0;" :: "n"(N));
}

__device__ __forceinline__ void mma_tf32(float c[4],
                                         unsigned a0, unsigned a1, unsigned a2, unsigned a3,
                                         unsigned b0, unsigned b1)
{
    asm("mma.sync.aligned.m16n8k8.row.col.f32.tf32.tf32.f32 "
        "{%0,%1,%2,%3},{%4,%5,%6,%7},{%8,%9},{%0,%1,%2,%3};"
        : "+f"(c[0]), "+f"(c[1]), "+f"(c[2]), "+f"(c[3])
        : "r"(a0), "r"(a1), "r"(a2), "r"(a3), "r"(b0), "r"(b1));
}

// TRANS_B=true : B is [K][N] row-major (NN gemm)
// TRANS_B=false: B is [N][K] row-major (NT gemm)
template<bool TRANS_B>
__device__ __forceinline__ void gemm_mma_core(const float* __restrict__ A,
                                              const float* __restrict__ B,
                                              int K, int lda, int ldb,
                                              float acc[4][4][4])
{
    extern __shared__ unsigned dynsmem[];
    unsigned* As = dynsmem;                          // 2 bufs
    unsigned* Bs = dynsmem + 2 * A_WORDS_BUF;        // 2 bufs

    const int tid  = threadIdx.x;
    const int lane = tid & 31;
    const int warp = tid >> 5;
    const int wm   = warp >> 2;        // 0..1
    const int wn   = warp & 3;         // 0..3
    const int lq   = lane >> 2;        // 0..7
    const int lr   = lane & 3;         // 0..3

    // ---- tile copy (cp.async, 16B chunks) ----
    auto copy_tiles = [&](int k0, int buf) {
        unsigned* as = As + buf * A_WORDS_BUF;
        // A: 128 rows x 32 k = 1024 chunks of 16B -> 4 per thread
        #pragma unroll
        for (int it = 0; it < 4; it++) {
            int idx  = it * 256 + tid;
            int row  = idx >> 3;
            int col4 = (idx & 7) * 4;
            cp16(&as[row * SLDA + col4], &A[(long)row * lda + k0 + col4]);
        }
        if (TRANS_B) {
            // B[K][N]: 32 k-rows x 128 n = 4096 words = 1024 chunks -> 4/thread
            unsigned* bs = Bs + buf * BNN_WORDS_BUF;
            #pragma unroll
            for (int it = 0; it < 4; it++) {
                int idx = it * 256 + tid;       // 0..1023
                int kr  = idx >> 5;             // 0..31
                int n4  = (idx & 31) * 4;       // 0..124
                cp16(&bs[kr * SLDB + n4], &B[(long)(k0 + kr) * ldb + n4]);
            }
        } else {
            // B[N][K]: same shape as A
            unsigned* bs = Bs + buf * BNT_WORDS_BUF;
            #pragma unroll
            for (int it = 0; it < 4; it++) {
                int idx  = it * 256 + tid;
                int row  = idx >> 3;
                int col4 = (idx & 7) * 4;
                cp16(&bs[row * SLDA + col4], &B[(long)row * ldb + k0 + col4]);
            }
        }
    };

    // ---- compute one staged tile ----
    auto compute_tile = [&](int buf) {
        const unsigned* as = As + buf * A_WORDS_BUF;
        const unsigned* bs = Bs + buf * (TRANS_B ? BNN_WORDS_BUF : BNT_WORDS_BUF);
        #pragma unroll
        for (int kk = 0; kk < 4; kk++) {
            const int kb = kk * 8;
            unsigned af[4][4], bf[4][2];
            #pragma unroll
            for (int mf = 0; mf < 4; mf++) {
                const unsigned* ap = &as[(wm * 64 + mf * 16 + lq) * SLDA + kb + lr];
                af[mf][0] = ap[0];
                af[mf][1] = ap[8 * SLDA];
                af[mf][2] = ap[4];
                af[mf][3] = ap[8 * SLDA + 4];
            }
            #pragma unroll
            for (int nf = 0; nf < 4; nf++) {
                const int nn = wn * 32 + nf * 8 + lq;
                if (TRANS_B) {
                    bf[nf][0] = bs[(kb + lr)     * SLDB + nn];
                    bf[nf][1] = bs[(kb + lr + 4) * SLDB + nn];
                } else {
                    bf[nf][0] = bs[nn * SLDA + kb + lr];
                    bf[nf][1] = bs[nn * SLDA + kb + lr + 4];
                }
            }
            #pragma unroll
            for (int mf = 0; mf < 4; mf++)
                #pragma unroll
                for (int nf = 0; nf < 4; nf++)
                    mma_tf32(acc[mf][nf], af[mf][0], af[mf][1], af[mf][2], af[mf][3],
                             bf[nf][0], bf[nf][1]);
        }
    };

    const int nit = K / BK;
    copy_tiles(0, 0);
    cp_commit();
    for (int it = 0; it < nit; it++) {
        const int buf = it & 1;
        if (it + 1 < nit) {
            copy_tiles((it + 1) * BK, buf ^ 1);
            cp_commit();
            cp_wait<1>();
        } else {
            cp_wait<0>();
        }
        __syncthreads();
        compute_tile(buf);
        __syncthreads();
    }
}

// Epilogue coords: frag (mf,nf), lane: row = wm*64+mf*16+lane/4 (+8 for c2/c3),
//                  col = wn*32+nf*8+2*(lane%4) (+1 for c1/c3)

// ---------------------------------------------------------------------------
// QKV GEMM: [NTOK,512] x [512,1536] + bias -> g_q/g_k/g_v
// ---------------------------------------------------------------------------
__global__ __launch_bounds__(256) void qkv_gemm_kernel(const float* __restrict__ w,
                                                       const float* __restrict__ bias)
{
    const int n0 = blockIdx.x * 128;
    const int m0 = blockIdx.y * 128;
    float acc[4][4][4] = {};
    gemm_mma_core<true>(g_h + (long)m0 * C, w + n0, C, C, QKVN, acc);

    const int lane = threadIdx.x & 31, warp = threadIdx.x >> 5;
    const int wm = warp >> 2, wn = warp & 3;
    const int which = n0 >> 9;   // 0=q 1=k 2=v
    float* dst = (which == 0) ? g_q : (which == 1) ? g_k : g_v;
    #pragma unroll
    for (int mf = 0; mf < 4; mf++) {
        const int r0 = m0 + wm * 64 + mf * 16 + (lane >> 2);
        #pragma unroll
        for (int nf = 0; nf < 4; nf++) {
            const int n = n0 + wn * 32 + nf * 8 + 2 * (lane & 3);
            const int c = n & 511;
            float b0 = bias[n], b1 = bias[n + 1];
            *reinterpret_cast<float2*>(&dst[(long)r0 * C + c]) =
                make_float2(acc[mf][nf][0] + b0, acc[mf][nf][1] + b1);
            *reinterpret_cast<float2*>(&dst[(long)(r0 + 8) * C + c]) =
                make_float2(acc[mf][nf][2] + b0, acc[mf][nf][3] + b1);
        }
    }
}

// ---------------------------------------------------------------------------
// scores[b,m,n] = scale * q[b,m,:] . k[b,n,:]   (NT)
// ---------------------------------------------------------------------------
__global__ __launch_bounds__(256) void scores_kernel()
{
    const int b  = blockIdx.z;
    const int n0 = blockIdx.x * 128;
    const int m0 = blockIdx.y * 128;
    const float scale = rsqrtf((float)C);

    float acc[4][4][4] = {};
    gemm_mma_core<false>(g_q + (long)b * HW * C + (long)m0 * C,
                         g_k + (long)b * HW * C + (long)n0 * C, C, C, C, acc);

    float* out = g_scores + (long)b * HW * HW;
    const int lane = threadIdx.x & 31, warp = threadIdx.x >> 5;
    const int wm = warp >> 2, wn = warp & 3;
    #pragma unroll
    for (int mf = 0; mf < 4; mf++) {
        const int r0 = m0 + wm * 64 + mf * 16 + (lane >> 2);
        #pragma unroll
        for (int nf = 0; nf < 4; nf++) {
            const int n = n0 + wn * 32 + nf * 8 + 2 * (lane & 3);
            *reinterpret_cast<float2*>(&out[(long)r0 * HW + n]) =
                make_float2(acc[mf][nf][0] * scale, acc[mf][nf][1] * scale);
            *reinterpret_cast<float2*>(&out[(long)(r0 + 8) * HW + n]) =
                make_float2(acc[mf][nf][2] * scale, acc[mf][nf][3] * scale);
        }
    }
}

// ---------------------------------------------------------------------------
// Row softmax over 1024 entries: 256 threads, float4 + shuffle reductions.
// ---------------------------------------------------------------------------
__global__ void softmax_kernel()
{
    __shared__ float wred[8];
    float4* p = reinterpret_cast<float4*>(g_scores + (long)blockIdx.x * HW);
    const int t    = threadIdx.x;
    const int lane = t & 31;
    const int warp = t >> 5;

    float4 v = p[t];
    float mx = fmaxf(fmaxf(v.x, v.y), fmaxf(v.z, v.w));
    #pragma unroll
    for (int o = 16; o > 0; o >>= 1)
        mx = fmaxf(mx, __shfl_xor_sync(0xffffffffu, mx, o));
    if (lane == 0) wred[warp] = mx;
    __syncthreads();
    mx = wred[0];
    #pragma unroll
    for (int i = 1; i < 8; i++) mx = fmaxf(mx, wred[i]);
    __syncthreads();

    v.x = __expf(v.x - mx); v.y = __expf(v.y - mx);
    v.z = __expf(v.z - mx); v.w = __expf(v.w - mx);
    float s = v.x + v.y + v.z + v.w;
    #pragma unroll
    for (int o = 16; o > 0; o >>= 1)
        s += __shfl_xor_sync(0xffffffffu, s, o);
    if (lane == 0) wred[warp] = s;
    __syncthreads();
    s = wred[0];
    #pragma unroll
    for (int i = 1; i < 8; i++) s += wred[i];

    const float inv = 1.0f / s;
    v.x *= inv; v.y *= inv; v.z *= inv; v.w *= inv;
    p[t] = v;
}

// ---------------------------------------------------------------------------
// attention output: g_h[b,m,c] = sum_n attn[b,m,n] * v[b,n,c]  (NN)
// ---------------------------------------------------------------------------
__global__ __launch_bounds__(256) void av_kernel()
{
    const int b  = blockIdx.z;
    const int n0 = blockIdx.x * 128;   // channel tile
    const int m0 = blockIdx.y * 128;   // query tile

    float acc[4][4][4] = {};
    gemm_mma_core<true>(g_scores + (long)b * HW * HW + (long)m0 * HW,
                        g_v + (long)b * HW * C + n0, HW, HW, C, acc);

    float* out = g_h + (long)b * HW * C;
    const int lane = threadIdx.x & 31, warp = threadIdx.x >> 5;
    const int wm = warp >> 2, wn = warp & 3;
    #pragma unroll
    for (int mf = 0; mf < 4; mf++) {
        const int r0 = m0 + wm * 64 + mf * 16 + (lane >> 2);
        #pragma unroll
        for (int nf = 0; nf < 4; nf++) {
            const int n = n0 + wn * 32 + nf * 8 + 2 * (lane & 3);
            *reinterpret_cast<float2*>(&out[(long)r0 * C + n]) =
                make_float2(acc[mf][nf][0], acc[mf][nf][1]);
            *reinterpret_cast<float2*>(&out[(long)(r0 + 8) * C + n]) =
                make_float2(acc[mf][nf][2], acc[mf][nf][3]);
        }
    }
}

// ---------------------------------------------------------------------------
// proj + bias + residual: out = x + g_h @ w_proj + b_proj
// ---------------------------------------------------------------------------
__global__ __launch_bounds__(256) void proj_kernel(const float* __restrict__ x,
                                                   const float* __restrict__ w,
                                                   const float* __restrict__ bias,
                                                   float* __restrict__ out)
{
    const int n0 = blockIdx.x * 128;
    const int m0 = blockIdx.y * 128;
    float acc[4][4][4] = {};
    gemm_mma_core<true>(g_h + (long)m0 * C, w + n0, C, C, C, acc);

    const int lane = threadIdx.x & 31, warp = threadIdx.x >> 5;
    const int wm = warp >> 2, wn = warp & 3;
    #pragma unroll
    for (int mf = 0; mf < 4; mf++) {
        const int r0 = m0 + wm * 64 + mf * 16 + (lane >> 2);
        #pragma unroll
        for (int nf = 0; nf < 4; nf++) {
            const int n = n0 + wn * 32 + nf * 8 + 2 * (lane & 3);
            float b0 = bias[n], b1 = bias[n + 1];
            float2 x0 = *reinterpret_cast<const float2*>(&x[(long)r0 * C + n]);
            float2 x1 = *reinterpret_cast<const float2*>(&x[(long)(r0 + 8) * C + n]);
            *reinterpret_cast<float2*>(&out[(long)r0 * C + n]) =
                make_float2(acc[mf][nf][0] + b0 + x0.x, acc[mf][nf][1] + b1 + x0.y);
            *reinterpret_cast<float2*>(&out[(long)(r0 + 8) * C + n]) =
                make_float2(acc[mf][nf][2] + b0 + x1.x, acc[mf][nf][3] + b1 + x1.y);
        }
    }
}

// ---------------------------------------------------------------------------
extern "C" void kernel_launch(void* const* d_in, const int* in_sizes, int n_in,
                              void* d_out, int out_size)
{
    const float* x      = (const float*)d_in[0];
    const float* gamma  = (const float*)d_in[1];
    const float* beta   = (const float*)d_in[2];
    const float* w_qkv  = (const float*)d_in[3];
    const float* b_qkv  = (const float*)d_in[4];
    const float* w_proj = (const float*)d_in[5];
    const float* b_proj = (const float*)d_in[6];
    float* out = (float*)d_out;

    // Opt-in to >48KB dynamic smem (idempotent, capture-safe, no allocation).
    cudaFuncSetAttribute(qkv_gemm_kernel, cudaFuncAttributeMaxDynamicSharedMemorySize, SMEM_BYTES_NN);
    cudaFuncSetAttribute(scores_kernel,   cudaFuncAttributeMaxDynamicSharedMemorySize, SMEM_BYTES_NT);
    cudaFuncSetAttribute(av_kernel,       cudaFuncAttributeMaxDynamicSharedMemorySize, SMEM_BYTES_NN);
    cudaFuncSetAttribute(proj_kernel,     cudaFuncAttributeMaxDynamicSharedMemorySize, SMEM_BYTES_NN);

    groupnorm_kernel<<<Bb * G, 256>>>(x, gamma, beta);
    qkv_gemm_kernel<<<dim3(QKVN / 128, NTOK / 128), 256, SMEM_BYTES_NN>>>(w_qkv, b_qkv);
    scores_kernel<<<dim3(HW / 128, HW / 128, Bb), 256, SMEM_BYTES_NT>>>();
    softmax_kernel<<<Bb * HW, 256>>>();
    av_kernel<<<dim3(C / 128, HW / 128, Bb), 256, SMEM_BYTES_NN>>>();
    proj_kernel<<<dim3(C / 128, NTOK / 128), 256, SMEM_BYTES_NN>>>(x, w_proj, b_proj, out);
}

// round 9
// speedup vs baseline: 3.9993x; 1.0608x over previous
#include <cuda_runtime.h>
#include <cuda_bf16.h>
#include <math.h>

// Problem constants
constexpr int Bb   = 32;          // batch
constexpr int HW   = 1024;        // H*W tokens per batch
constexpr int C    = 512;         // channels
constexpr int G    = 8;           // groups
constexpr int CG   = C / G;       // 64 channels per group
constexpr int NTOK = Bb * HW;     // 32768 total tokens
constexpr int QKVN = 3 * C;       // 1536
constexpr float EPS = 1e-3f;

// Scratch (device globals -> allowed; no allocations). ~384 MB total.
__device__ float g_h [ (long)NTOK * C ];           // 64 MB (normed in, then attn out)
__device__ float g_q [ (long)NTOK * C ];           // 64 MB
__device__ float g_k [ (long)NTOK * C ];           // 64 MB
__device__ float g_v [ (long)NTOK * C ];           // 64 MB
__device__ float g_scores[ (long)Bb * HW * HW ];   // 128 MB (holds exp(scale*s))
__device__ float g_rowsum[ NTOK ];                 // 128 KB per-row sum of exp

// ---------------------------------------------------------------------------
// Zero the row-sum accumulator (must run every launch; graph-replay safe).
// ---------------------------------------------------------------------------
__global__ void zero_rowsum_kernel()
{
    g_rowsum[blockIdx.x * 256 + threadIdx.x] = 0.0f;
}

// ---------------------------------------------------------------------------
// GroupNorm (float4 paths; 64-channel group slices are 16-float4 aligned)
// ---------------------------------------------------------------------------
__global__ void groupnorm_kernel(const float* __restrict__ x,
                                 const float* __restrict__ gamma,
                                 const float* __restrict__ beta)
{
    const int bg = blockIdx.x;
    const int b  = bg >> 3;
    const int g  = bg & 7;
    const int t  = threadIdx.x;         // 256 threads

    const long base = ((long)b * HW) * C + g * CG;

    __shared__ float s_sum[256];
    __shared__ float s_sq [256];

    float lsum = 0.f, lsq = 0.f;
    for (int idx = t; idx < HW * CG / 4; idx += 256) {
        int n  = idx >> 4;              // token
        int c4 = (idx & 15) * 4;        // channel (vec4) within group
        float4 v = *reinterpret_cast<const float4*>(&x[base + (long)n * C + c4]);
        lsum += v.x + v.y + v.z + v.w;
        lsq  += v.x*v.x + v.y*v.y + v.z*v.z + v.w*v.w;
    }
    s_sum[t] = lsum; s_sq[t] = lsq;
    __syncthreads();
    for (int s = 128; s > 0; s >>= 1) {
        if (t < s) { s_sum[t] += s_sum[t + s]; s_sq[t] += s_sq[t + s]; }
        __syncthreads();
    }
    const float inv_n = 1.0f / (HW * CG);
    const float mean  = s_sum[0] * inv_n;
    const float var   = s_sq[0] * inv_n - mean * mean;
    const float rstd  = rsqrtf(var + EPS);

    for (int idx = t; idx < HW * CG / 4; idx += 256) {
        int n  = idx >> 4;
        int c4 = (idx & 15) * 4;
        int gc = g * CG + c4;
        float4 v  = *reinterpret_cast<const float4*>(&x[base + (long)n * C + c4]);
        float4 gm = *reinterpret_cast<const float4*>(&gamma[gc]);
        float4 bt = *reinterpret_cast<const float4*>(&beta[gc]);
        float4 o;
        o.x = (v.x - mean) * rstd * gm.x + bt.x;
        o.y = (v.y - mean) * rstd * gm.y + bt.y;
        o.z = (v.z - mean) * rstd * gm.z + bt.z;
        o.w = (v.w - mean) * rstd * gm.w + bt.w;
        *reinterpret_cast<float4*>(&g_h[base + (long)n * C + c4]) = o;
    }
}

// ---------------------------------------------------------------------------
// TF32 tensor-core GEMM core, cp.async double-buffered.
// Block tile 128x128, BK=32, 256 threads = 8 warps (2x4), warp tile 64x32.
// Raw fp32 bits are fed to mma.tf32 (HW truncates mantissa).
// Smem: As[2][128][36]  (rows = M, cols = K, stride 36 => conflict-free frags)
//       NT-B (B=[N][K]): Bs[2][128][36] like A
//       NN-B (B=[K][N]): Bs[2][32][136] k-major (no transpose needed)
// ---------------------------------------------------------------------------
constexpr int BK   = 32;
constexpr int SLDA = 36;    // A / NT-B smem row stride (words)
constexpr int SLDB = 136;   // NN-B smem row stride (words)

constexpr int A_WORDS_BUF  = 128 * SLDA;          // 4608
constexpr int BNT_WORDS_BUF= 128 * SLDA;          // 4608
constexpr int BNN_WORDS_BUF= BK * SLDB;           // 4352
constexpr int SMEM_BYTES_NT = (2*A_WORDS_BUF + 2*BNT_WORDS_BUF) * 4;  // 73728
constexpr int SMEM_BYTES_NN = (2*A_WORDS_BUF + 2*BNN_WORDS_BUF) * 4;  // 71680

__device__ __forceinline__ void cp16(unsigned* dst_smem, const float* src) {
    unsigned s = (unsigned)__cvta_generic_to_shared(dst_smem);
    asm volatile("cp.async.cg.shared.global [%0], [%1], 16;" :: "r"(s), "l"(src));
}
__device__ __forceinline__ void cp_commit() {
    asm volatile("cp.async.commit_group;");
}
template<int N>
__device__ __forceinline__ void cp_wait() {
    asm volatile("cp.async.wait_group %0;" :: "n"(N));
}

__device__ __forceinline__ void mma_tf32(float c[4],
                                         unsigned a0, unsigned a1, unsigned a2, unsigned a3,
                                         unsigned b0, unsigned b1)
{
    asm("mma.sync.aligned.m16n8k8.row.col.f32.tf32.tf32.f32 "
        "{%0,%1,%2,%3},{%4,%5,%6,%7},{%8,%9},{%0,%1,%2,%3};"
        : "+f"(c[0]), "+f"(c[1]), "+f"(c[2]), "+f"(c[3])
        : "r"(a0), "r"(a1), "r"(a2), "r"(a3), "r"(b0), "r"(b1));
}

// TRANS_B=true : B is [K][N] row-major (NN gemm)
// TRANS_B=false: B is [N][K] row-major (NT gemm)
template<bool TRANS_B>
__device__ __forceinline__ void gemm_mma_core(const float* __restrict__ A,
                                              const float* __restrict__ B,
                                              int K, int lda, int ldb,
                                              float acc[4][4][4])
{
    extern __shared__ unsigned dynsmem[];
    unsigned* As = dynsmem;                          // 2 bufs
    unsigned* Bs = dynsmem + 2 * A_WORDS_BUF;        // 2 bufs

    const int tid  = threadIdx.x;
    const int lane = tid & 31;
    const int warp = tid >> 5;
    const int wm   = warp >> 2;        // 0..1
    const int wn   = warp & 3;         // 0..3
    const int lq   = lane >> 2;        // 0..7
    const int lr   = lane & 3;         // 0..3

    // ---- tile copy (cp.async, 16B chunks) ----
    auto copy_tiles = [&](int k0, int buf) {
        unsigned* as = As + buf * A_WORDS_BUF;
        #pragma unroll
        for (int it = 0; it < 4; it++) {
            int idx  = it * 256 + tid;
            int row  = idx >> 3;
            int col4 = (idx & 7) * 4;
            cp16(&as[row * SLDA + col4], &A[(long)row * lda + k0 + col4]);
        }
        if (TRANS_B) {
            unsigned* bs = Bs + buf * BNN_WORDS_BUF;
            #pragma unroll
            for (int it = 0; it < 4; it++) {
                int idx = it * 256 + tid;       // 0..1023
                int kr  = idx >> 5;             // 0..31
                int n4  = (idx & 31) * 4;       // 0..124
                cp16(&bs[kr * SLDB + n4], &B[(long)(k0 + kr) * ldb + n4]);
            }
        } else {
            unsigned* bs = Bs + buf * BNT_WORDS_BUF;
            #pragma unroll
            for (int it = 0; it < 4; it++) {
                int idx  = it * 256 + tid;
                int row  = idx >> 3;
                int col4 = (idx & 7) * 4;
                cp16(&bs[row * SLDA + col4], &B[(long)row * ldb + k0 + col4]);
            }
        }
    };

    // ---- compute one staged tile ----
    auto compute_tile = [&](int buf) {
        const unsigned* as = As + buf * A_WORDS_BUF;
        const unsigned* bs = Bs + buf * (TRANS_B ? BNN_WORDS_BUF : BNT_WORDS_BUF);
        #pragma unroll
        for (int kk = 0; kk < 4; kk++) {
            const int kb = kk * 8;
            unsigned af[4][4], bf[4][2];
            #pragma unroll
            for (int mf = 0; mf < 4; mf++) {
                const unsigned* ap = &as[(wm * 64 + mf * 16 + lq) * SLDA + kb + lr];
                af[mf][0] = ap[0];
                af[mf][1] = ap[8 * SLDA];
                af[mf][2] = ap[4];
                af[mf][3] = ap[8 * SLDA + 4];
            }
            #pragma unroll
            for (int nf = 0; nf < 4; nf++) {
                const int nn = wn * 32 + nf * 8 + lq;
                if (TRANS_B) {
                    bf[nf][0] = bs[(kb + lr)     * SLDB + nn];
                    bf[nf][1] = bs[(kb + lr + 4) * SLDB + nn];
                } else {
                    bf[nf][0] = bs[nn * SLDA + kb + lr];
                    bf[nf][1] = bs[nn * SLDA + kb + lr + 4];
                }
            }
            #pragma unroll
            for (int mf = 0; mf < 4; mf++)
                #pragma unroll
                for (int nf = 0; nf < 4; nf++)
                    mma_tf32(acc[mf][nf], af[mf][0], af[mf][1], af[mf][2], af[mf][3],
                             bf[nf][0], bf[nf][1]);
        }
    };

    const int nit = K / BK;
    copy_tiles(0, 0);
    cp_commit();
    for (int it = 0; it < nit; it++) {
        const int buf = it & 1;
        if (it + 1 < nit) {
            copy_tiles((it + 1) * BK, buf ^ 1);
            cp_commit();
            cp_wait<1>();
        } else {
            cp_wait<0>();
        }
        __syncthreads();
        compute_tile(buf);
        __syncthreads();
    }
}

// Epilogue coords: frag (mf,nf), lane: row = wm*64+mf*16+lane/4 (+8 for c2/c3),
//                  col = wn*32+nf*8+2*(lane%4) (+1 for c1/c3)

// ---------------------------------------------------------------------------
// QKV GEMM: [NTOK,512] x [512,1536] + bias -> g_q/g_k/g_v
// ---------------------------------------------------------------------------
__global__ __launch_bounds__(256) void qkv_gemm_kernel(const float* __restrict__ w,
                                                       const float* __restrict__ bias)
{
    const int n0 = blockIdx.x * 128;
    const int m0 = blockIdx.y * 128;
    float acc[4][4][4] = {};
    gemm_mma_core<true>(g_h + (long)m0 * C, w + n0, C, C, QKVN, acc);

    const int lane = threadIdx.x & 31, warp = threadIdx.x >> 5;
    const int wm = warp >> 2, wn = warp & 3;
    const int which = n0 >> 9;   // 0=q 1=k 2=v
    float* dst = (which == 0) ? g_q : (which == 1) ? g_k : g_v;
    #pragma unroll
    for (int mf = 0; mf < 4; mf++) {
        const int r0 = m0 + wm * 64 + mf * 16 + (lane >> 2);
        #pragma unroll
        for (int nf = 0; nf < 4; nf++) {
            const int n = n0 + wn * 32 + nf * 8 + 2 * (lane & 3);
            const int c = n & 511;
            float b0 = bias[n], b1 = bias[n + 1];
            *reinterpret_cast<float2*>(&dst[(long)r0 * C + c]) =
                make_float2(acc[mf][nf][0] + b0, acc[mf][nf][1] + b1);
            *reinterpret_cast<float2*>(&dst[(long)(r0 + 8) * C + c]) =
                make_float2(acc[mf][nf][2] + b0, acc[mf][nf][3] + b1);
        }
    }
}

// ---------------------------------------------------------------------------
// scores: p[b,m,n] = exp(scale * q.k) stored unnormalized; row sums via atomics.
// (Max-subtraction is unnecessary here: scores ~ N(0,1), |s| < ~6 << 88.)
// ---------------------------------------------------------------------------
__global__ __launch_bounds__(256) void scores_kernel()
{
    const int b  = blockIdx.z;
    const int n0 = blockIdx.x * 128;
    const int m0 = blockIdx.y * 128;
    const float scale = rsqrtf((float)C);

    float acc[4][4][4] = {};
    gemm_mma_core<false>(g_q + (long)b * HW * C + (long)m0 * C,
                         g_k + (long)b * HW * C + (long)n0 * C, C, C, C, acc);

    float* out = g_scores + (long)b * HW * HW;
    const int lane = threadIdx.x & 31, warp = threadIdx.x >> 5;
    const int wm = warp >> 2, wn = warp & 3;
    const int lr = lane & 3;
    #pragma unroll
    for (int mf = 0; mf < 4; mf++) {
        const int r0 = m0 + wm * 64 + mf * 16 + (lane >> 2);
        float sum0 = 0.f, sum8 = 0.f;
        #pragma unroll
        for (int nf = 0; nf < 4; nf++) {
            const int n = n0 + wn * 32 + nf * 8 + 2 * lr;
            float e0 = __expf(acc[mf][nf][0] * scale);
            float e1 = __expf(acc[mf][nf][1] * scale);
            float e2 = __expf(acc[mf][nf][2] * scale);
            float e3 = __expf(acc[mf][nf][3] * scale);
            *reinterpret_cast<float2*>(&out[(long)r0 * HW + n])       = make_float2(e0, e1);
            *reinterpret_cast<float2*>(&out[(long)(r0 + 8) * HW + n]) = make_float2(e2, e3);
            sum0 += e0 + e1;
            sum8 += e2 + e3;
        }
        // reduce over the 4 lanes sharing this row (lr = 0..3)
        #pragma unroll
        for (int o = 1; o < 4; o <<= 1) {
            sum0 += __shfl_xor_sync(0xffffffffu, sum0, o);
            sum8 += __shfl_xor_sync(0xffffffffu, sum8, o);
        }
        if (lr == 0) {
            atomicAdd(&g_rowsum[b * HW + r0],     sum0);
            atomicAdd(&g_rowsum[b * HW + r0 + 8], sum8);
        }
    }
}

// ---------------------------------------------------------------------------
// attention output: g_h[b,m,c] = (sum_n p[b,m,n] * v[b,n,c]) / rowsum[b,m]
// ---------------------------------------------------------------------------
__global__ __launch_bounds__(256) void av_kernel()
{
    const int b  = blockIdx.z;
    const int n0 = blockIdx.x * 128;   // channel tile
    const int m0 = blockIdx.y * 128;   // query tile

    float acc[4][4][4] = {};
    gemm_mma_core<true>(g_scores + (long)b * HW * HW + (long)m0 * HW,
                        g_v + (long)b * HW * C + n0, HW, HW, C, acc);

    float* out = g_h + (long)b * HW * C;
    const int lane = threadIdx.x & 31, warp = threadIdx.x >> 5;
    const int wm = warp >> 2, wn = warp & 3;
    #pragma unroll
    for (int mf = 0; mf < 4; mf++) {
        const int r0 = m0 + wm * 64 + mf * 16 + (lane >> 2);
        const float inv0 = 1.0f / g_rowsum[b * HW + r0];
        const float inv8 = 1.0f / g_rowsum[b * HW + r0 + 8];
        #pragma unroll
        for (int nf = 0; nf < 4; nf++) {
            const int n = n0 + wn * 32 + nf * 8 + 2 * (lane & 3);
            *reinterpret_cast<float2*>(&out[(long)r0 * C + n]) =
                make_float2(acc[mf][nf][0] * inv0, acc[mf][nf][1] * inv0);
            *reinterpret_cast<float2*>(&out[(long)(r0 + 8) * C + n]) =
                make_float2(acc[mf][nf][2] * inv8, acc[mf][nf][3] * inv8);
        }
    }
}

// ---------------------------------------------------------------------------
// proj + bias + residual: out = x + g_h @ w_proj + b_proj
// ---------------------------------------------------------------------------
__global__ __launch_bounds__(256) void proj_kernel(const float* __restrict__ x,
                                                   const float* __restrict__ w,
                                                   const float* __restrict__ bias,
                                                   float* __restrict__ out)
{
    const int n0 = blockIdx.x * 128;
    const int m0 = blockIdx.y * 128;
    float acc[4][4][4] = {};
    gemm_mma_core<true>(g_h + (long)m0 * C, w + n0, C, C, C, acc);

    const int lane = threadIdx.x & 31, warp = threadIdx.x >> 5;
    const int wm = warp >> 2, wn = warp & 3;
    #pragma unroll
    for (int mf = 0; mf < 4; mf++) {
        const int r0 = m0 + wm * 64 + mf * 16 + (lane >> 2);
        #pragma unroll
        for (int nf = 0; nf < 4; nf++) {
            const int n = n0 + wn * 32 + nf * 8 + 2 * (lane & 3);
            float b0 = bias[n], b1 = bias[n + 1];
            float2 x0 = *reinterpret_cast<const float2*>(&x[(long)r0 * C + n]);
            float2 x1 = *reinterpret_cast<const float2*>(&x[(long)(r0 + 8) * C + n]);
            *reinterpret_cast<float2*>(&out[(long)r0 * C + n]) =
                make_float2(acc[mf][nf][0] + b0 + x0.x, acc[mf][nf][1] + b1 + x0.y);
            *reinterpret_cast<float2*>(&out[(long)(r0 + 8) * C + n]) =
                make_float2(acc[mf][nf][2] + b0 + x1.x, acc[mf][nf][3] + b1 + x1.y);
        }
    }
}

// ---------------------------------------------------------------------------
extern "C" void kernel_launch(void* const* d_in, const int* in_sizes, int n_in,
                              void* d_out, int out_size)
{
    const float* x      = (const float*)d_in[0];
    const float* gamma  = (const float*)d_in[1];
    const float* beta   = (const float*)d_in[2];
    const float* w_qkv  = (const float*)d_in[3];
    const float* b_qkv  = (const float*)d_in[4];
    const float* w_proj = (const float*)d_in[5];
    const float* b_proj = (const float*)d_in[6];
    float* out = (float*)d_out;

    // Opt-in to >48KB dynamic smem (idempotent, capture-safe, no allocation).
    cudaFuncSetAttribute(qkv_gemm_kernel, cudaFuncAttributeMaxDynamicSharedMemorySize, SMEM_BYTES_NN);
    cudaFuncSetAttribute(scores_kernel,   cudaFuncAttributeMaxDynamicSharedMemorySize, SMEM_BYTES_NT);
    cudaFuncSetAttribute(av_kernel,       cudaFuncAttributeMaxDynamicSharedMemorySize, SMEM_BYTES_NN);
    cudaFuncSetAttribute(proj_kernel,     cudaFuncAttributeMaxDynamicSharedMemorySize, SMEM_BYTES_NN);

    zero_rowsum_kernel<<<NTOK / 256, 256>>>();
    groupnorm_kernel<<<Bb * G, 256>>>(x, gamma, beta);
    qkv_gemm_kernel<<<dim3(QKVN / 128, NTOK / 128), 256, SMEM_BYTES_NN>>>(w_qkv, b_qkv);
    scores_kernel<<<dim3(HW / 128, HW / 128, Bb), 256, SMEM_BYTES_NT>>>();
    av_kernel<<<dim3(C / 128, HW / 128, Bb), 256, SMEM_BYTES_NN>>>();
    proj_kernel<<<dim3(C / 128, NTOK / 128), 256, SMEM_BYTES_NN>>>(x, w_proj, b_proj, out);
}

// round 10
// speedup vs baseline: 4.0068x; 1.0019x over previous
#include <cuda_runtime.h>
#include <cuda_bf16.h>
#include <math.h>

// Problem constants
constexpr int Bb   = 32;          // batch
constexpr int HW   = 1024;        // H*W tokens per batch
constexpr int C    = 512;         // channels
constexpr int G    = 8;           // groups
constexpr int CG   = C / G;       // 64 channels per group
constexpr int NTOK = Bb * HW;     // 32768 total tokens
constexpr int QKVN = 3 * C;       // 1536
constexpr float EPS = 1e-3f;

// Scratch (device globals -> allowed; no allocations). ~384 MB total.
__device__ float g_h [ (long)NTOK * C ];           // 64 MB (normed in, then attn out)
__device__ float g_q [ (long)NTOK * C ];           // 64 MB
__device__ float g_k [ (long)NTOK * C ];           // 64 MB
__device__ float g_v [ (long)NTOK * C ];           // 64 MB
__device__ float g_scores[ (long)Bb * HW * HW ];   // 128 MB (holds exp(scale*s))
__device__ float g_rowsum[ NTOK ];                 // 128 KB per-row sum of exp

// ---------------------------------------------------------------------------
// Zero the row-sum accumulator (must run every launch; graph-replay safe).
// ---------------------------------------------------------------------------
__global__ void zero_rowsum_kernel()
{
    g_rowsum[blockIdx.x * 256 + threadIdx.x] = 0.0f;
}

// ---------------------------------------------------------------------------
// GroupNorm (float4 paths; 64-channel group slices are 16-float4 aligned)
// ---------------------------------------------------------------------------
__global__ void groupnorm_kernel(const float* __restrict__ x,
                                 const float* __restrict__ gamma,
                                 const float* __restrict__ beta)
{
    const int bg = blockIdx.x;
    const int b  = bg >> 3;
    const int g  = bg & 7;
    const int t  = threadIdx.x;         // 256 threads

    const long base = ((long)b * HW) * C + g * CG;

    __shared__ float s_sum[256];
    __shared__ float s_sq [256];

    float lsum = 0.f, lsq = 0.f;
    for (int idx = t; idx < HW * CG / 4; idx += 256) {
        int n  = idx >> 4;              // token
        int c4 = (idx & 15) * 4;        // channel (vec4) within group
        float4 v = *reinterpret_cast<const float4*>(&x[base + (long)n * C + c4]);
        lsum += v.x + v.y + v.z + v.w;
        lsq  += v.x*v.x + v.y*v.y + v.z*v.z + v.w*v.w;
    }
    s_sum[t] = lsum; s_sq[t] = lsq;
    __syncthreads();
    for (int s = 128; s > 0; s >>= 1) {
        if (t < s) { s_sum[t] += s_sum[t + s]; s_sq[t] += s_sq[t + s]; }
        __syncthreads();
    }
    const float inv_n = 1.0f / (HW * CG);
    const float mean  = s_sum[0] * inv_n;
    const float var   = s_sq[0] * inv_n - mean * mean;
    const float rstd  = rsqrtf(var + EPS);

    for (int idx = t; idx < HW * CG / 4; idx += 256) {
        int n  = idx >> 4;
        int c4 = (idx & 15) * 4;
        int gc = g * CG + c4;
        float4 v  = *reinterpret_cast<const float4*>(&x[base + (long)n * C + c4]);
        float4 gm = *reinterpret_cast<const float4*>(&gamma[gc]);
        float4 bt = *reinterpret_cast<const float4*>(&beta[gc]);
        float4 o;
        o.x = (v.x - mean) * rstd * gm.x + bt.x;
        o.y = (v.y - mean) * rstd * gm.y + bt.y;
        o.z = (v.z - mean) * rstd * gm.z + bt.z;
        o.w = (v.w - mean) * rstd * gm.w + bt.w;
        *reinterpret_cast<float4*>(&g_h[base + (long)n * C + c4]) = o;
    }
}

// ---------------------------------------------------------------------------
// TF32 tensor-core GEMM core, cp.async double-buffered.
// Block tile 128x128, BK=32, 256 threads = 8 warps (2x4), warp tile 64x32.
// Raw fp32 bits are fed to mma.tf32 (HW truncates mantissa).
// Smem: As[2][128][36]  (rows = M, cols = K, stride 36 => conflict-free frags)
//       NT-B (B=[N][K]): Bs[2][128][36] like A
//       NN-B (B=[K][N]): Bs[2][32][136] k-major (no transpose needed)
// ---------------------------------------------------------------------------
constexpr int BK   = 32;
constexpr int SLDA = 36;    // A / NT-B smem row stride (words)
constexpr int SLDB = 136;   // NN-B smem row stride (words)

constexpr int A_WORDS_BUF  = 128 * SLDA;          // 4608
constexpr int BNT_WORDS_BUF= 128 * SLDA;          // 4608
constexpr int BNN_WORDS_BUF= BK * SLDB;           // 4352
constexpr int SMEM_BYTES_NT = (2*A_WORDS_BUF + 2*BNT_WORDS_BUF) * 4;  // 73728
constexpr int SMEM_BYTES_NN = (2*A_WORDS_BUF + 2*BNN_WORDS_BUF) * 4;  // 71680

__device__ __forceinline__ void cp16(unsigned* dst_smem, const float* src) {
    unsigned s = (unsigned)__cvta_generic_to_shared(dst_smem);
    asm volatile("cp.async.cg.shared.global [%0], [%1], 16;" :: "r"(s), "l"(src));
}
__device__ __forceinline__ void cp_commit() {
    asm volatile("cp.async.commit_group;");
}
template<int N>
__device__ __forceinline__ void cp_wait() {
    asm volatile("cp.async.wait_group %0;" :: "n"(N));
}

__device__ __forceinline__ void mma_tf32(float c[4],
                                         unsigned a0, unsigned a1, unsigned a2, unsigned a3,
                                         unsigned b0, unsigned b1)
{
    asm("mma.sync.aligned.m16n8k8.row.col.f32.tf32.tf32.f32 "
        "{%0,%1,%2,%3},{%4,%5,%6,%7},{%8,%9},{%0,%1,%2,%3};"
        : "+f"(c[0]), "+f"(c[1]), "+f"(c[2]), "+f"(c[3])
        : "r"(a0), "r"(a1), "r"(a2), "r"(a3), "r"(b0), "r"(b1));
}

// TRANS_B=true : B is [K][N] row-major (NN gemm)
// TRANS_B=false: B is [N][K] row-major (NT gemm)
template<bool TRANS_B>
__device__ __forceinline__ void gemm_mma_core(const float* __restrict__ A,
                                              const float* __restrict__ B,
                                              int K, int lda, int ldb,
                                              float acc[4][4][4])
{
    extern __shared__ unsigned dynsmem[];
    unsigned* As = dynsmem;                          // 2 bufs
    unsigned* Bs = dynsmem + 2 * A_WORDS_BUF;        // 2 bufs

    const int tid  = threadIdx.x;
    const int lane = tid & 31;
    const int warp = tid >> 5;
    const int wm   = warp >> 2;        // 0..1
    const int wn   = warp & 3;         // 0..3
    const int lq   = lane >> 2;        // 0..7
    const int lr   = lane & 3;         // 0..3

    // ---- tile copy (cp.async, 16B chunks) ----
    auto copy_tiles = [&](int k0, int buf) {
        unsigned* as = As + buf * A_WORDS_BUF;
        #pragma unroll
        for (int it = 0; it < 4; it++) {
            int idx  = it * 256 + tid;
            int row  = idx >> 3;
            int col4 = (idx & 7) * 4;
            cp16(&as[row * SLDA + col4], &A[(long)row * lda + k0 + col4]);
        }
        if (TRANS_B) {
            unsigned* bs = Bs + buf * BNN_WORDS_BUF;
            #pragma unroll
            for (int it = 0; it < 4; it++) {
                int idx = it * 256 + tid;       // 0..1023
                int kr  = idx >> 5;             // 0..31
                int n4  = (idx & 31) * 4;       // 0..124
                cp16(&bs[kr * SLDB + n4], &B[(long)(k0 + kr) * ldb + n4]);
            }
        } else {
            unsigned* bs = Bs + buf * BNT_WORDS_BUF;
            #pragma unroll
            for (int it = 0; it < 4; it++) {
                int idx  = it * 256 + tid;
                int row  = idx >> 3;
                int col4 = (idx & 7) * 4;
                cp16(&bs[row * SLDA + col4], &B[(long)row * ldb + k0 + col4]);
            }
        }
    };

    // ---- compute one staged tile ----
    auto compute_tile = [&](int buf) {
        const unsigned* as = As + buf * A_WORDS_BUF;
        const unsigned* bs = Bs + buf * (TRANS_B ? BNN_WORDS_BUF : BNT_WORDS_BUF);
        #pragma unroll
        for (int kk = 0; kk < 4; kk++) {
            const int kb = kk * 8;
            unsigned af[4][4], bf[4][2];
            #pragma unroll
            for (int mf = 0; mf < 4; mf++) {
                const unsigned* ap = &as[(wm * 64 + mf * 16 + lq) * SLDA + kb + lr];
                af[mf][0] = ap[0];
                af[mf][1] = ap[8 * SLDA];
                af[mf][2] = ap[4];
                af[mf][3] = ap[8 * SLDA + 4];
            }
            #pragma unroll
            for (int nf = 0; nf < 4; nf++) {
                const int nn = wn * 32 + nf * 8 + lq;
                if (TRANS_B) {
                    bf[nf][0] = bs[(kb + lr)     * SLDB + nn];
                    bf[nf][1] = bs[(kb + lr + 4) * SLDB + nn];
                } else {
                    bf[nf][0] = bs[nn * SLDA + kb + lr];
                    bf[nf][1] = bs[nn * SLDA + kb + lr + 4];
                }
            }
            #pragma unroll
            for (int mf = 0; mf < 4; mf++)
                #pragma unroll
                for (int nf = 0; nf < 4; nf++)
                    mma_tf32(acc[mf][nf], af[mf][0], af[mf][1], af[mf][2], af[mf][3],
                             bf[nf][0], bf[nf][1]);
        }
    };

    const int nit = K / BK;
    copy_tiles(0, 0);
    cp_commit();
    for (int it = 0; it < nit; it++) {
        const int buf = it & 1;
        if (it + 1 < nit) {
            copy_tiles((it + 1) * BK, buf ^ 1);
            cp_commit();
            cp_wait<1>();
        } else {
            cp_wait<0>();
        }
        __syncthreads();
        compute_tile(buf);
        __syncthreads();
    }
}

// Epilogue coords: frag (mf,nf), lane: row = wm*64+mf*16+lane/4 (+8 for c2/c3),
//                  col = wn*32+nf*8+2*(lane%4) (+1 for c1/c3)

// ---------------------------------------------------------------------------
// QKV GEMM: [NTOK,512] x [512,1536] + bias -> g_q/g_k/g_v
// ---------------------------------------------------------------------------
__global__ __launch_bounds__(256) void qkv_gemm_kernel(const float* __restrict__ w,
                                                       const float* __restrict__ bias)
{
    const int n0 = blockIdx.x * 128;
    const int m0 = blockIdx.y * 128;
    float acc[4][4][4] = {};
    gemm_mma_core<true>(g_h + (long)m0 * C, w + n0, C, C, QKVN, acc);

    const int lane = threadIdx.x & 31, warp = threadIdx.x >> 5;
    const int wm = warp >> 2, wn = warp & 3;
    const int which = n0 >> 9;   // 0=q 1=k 2=v
    float* dst = (which == 0) ? g_q : (which == 1) ? g_k : g_v;
    #pragma unroll
    for (int mf = 0; mf < 4; mf++) {
        const int r0 = m0 + wm * 64 + mf * 16 + (lane >> 2);
        #pragma unroll
        for (int nf = 0; nf < 4; nf++) {
            const int n = n0 + wn * 32 + nf * 8 + 2 * (lane & 3);
            const int c = n & 511;
            float b0 = bias[n], b1 = bias[n + 1];
            *reinterpret_cast<float2*>(&dst[(long)r0 * C + c]) =
                make_float2(acc[mf][nf][0] + b0, acc[mf][nf][1] + b1);
            *reinterpret_cast<float2*>(&dst[(long)(r0 + 8) * C + c]) =
                make_float2(acc[mf][nf][2] + b0, acc[mf][nf][3] + b1);
        }
    }
}

// ---------------------------------------------------------------------------
// scores: p[b,m,n] = exp(scale * q.k) stored unnormalized; row sums via atomics.
// (Max-subtraction is unnecessary here: scores ~ N(0,1), |s| < ~6 << 88.)
// ---------------------------------------------------------------------------
__global__ __launch_bounds__(256) void scores_kernel()
{
    const int b  = blockIdx.z;
    const int n0 = blockIdx.x * 128;
    const int m0 = blockIdx.y * 128;
    const float scale = rsqrtf((float)C);

    float acc[4][4][4] = {};
    gemm_mma_core<false>(g_q + (long)b * HW * C + (long)m0 * C,
                         g_k + (long)b * HW * C + (long)n0 * C, C, C, C, acc);

    float* out = g_scores + (long)b * HW * HW;
    const int lane = threadIdx.x & 31, warp = threadIdx.x >> 5;
    const int wm = warp >> 2, wn = warp & 3;
    const int lr = lane & 3;
    #pragma unroll
    for (int mf = 0; mf < 4; mf++) {
        const int r0 = m0 + wm * 64 + mf * 16 + (lane >> 2);
        float sum0 = 0.f, sum8 = 0.f;
        #pragma unroll
        for (int nf = 0; nf < 4; nf++) {
            const int n = n0 + wn * 32 + nf * 8 + 2 * lr;
            float e0 = __expf(acc[mf][nf][0] * scale);
            float e1 = __expf(acc[mf][nf][1] * scale);
            float e2 = __expf(acc[mf][nf][2] * scale);
            float e3 = __expf(acc[mf][nf][3] * scale);
            *reinterpret_cast<float2*>(&out[(long)r0 * HW + n])       = make_float2(e0, e1);
            *reinterpret_cast<float2*>(&out[(long)(r0 + 8) * HW + n]) = make_float2(e2, e3);
            sum0 += e0 + e1;
            sum8 += e2 + e3;
        }
        // reduce over the 4 lanes sharing this row (lr = 0..3)
        #pragma unroll
        for (int o = 1; o < 4; o <<= 1) {
            sum0 += __shfl_xor_sync(0xffffffffu, sum0, o);
            sum8 += __shfl_xor_sync(0xffffffffu, sum8, o);
        }
        if (lr == 0) {
            atomicAdd(&g_rowsum[b * HW + r0],     sum0);
            atomicAdd(&g_rowsum[b * HW + r0 + 8], sum8);
        }
    }
}

// ---------------------------------------------------------------------------
// attention output: g_h[b,m,c] = (sum_n p[b,m,n] * v[b,n,c]) / rowsum[b,m]
// ---------------------------------------------------------------------------
__global__ __launch_bounds__(256) void av_kernel()
{
    const int b  = blockIdx.z;
    const int n0 = blockIdx.x * 128;   // channel tile
    const int m0 = blockIdx.y * 128;   // query tile

    float acc[4][4][4] = {};
    gemm_mma_core<true>(g_scores + (long)b * HW * HW + (long)m0 * HW,
                        g_v + (long)b * HW * C + n0, HW, HW, C, acc);

    float* out = g_h + (long)b * HW * C;
    const int lane = threadIdx.x & 31, warp = threadIdx.x >> 5;
    const int wm = warp >> 2, wn = warp & 3;
    #pragma unroll
    for (int mf = 0; mf < 4; mf++) {
        const int r0 = m0 + wm * 64 + mf * 16 + (lane >> 2);
        const float inv0 = 1.0f / g_rowsum[b * HW + r0];
        const float inv8 = 1.0f / g_rowsum[b * HW + r0 + 8];
        #pragma unroll
        for (int nf = 0; nf < 4; nf++) {
            const int n = n0 + wn * 32 + nf * 8 + 2 * (lane & 3);
            *reinterpret_cast<float2*>(&out[(long)r0 * C + n]) =
                make_float2(acc[mf][nf][0] * inv0, acc[mf][nf][1] * inv0);
            *reinterpret_cast<float2*>(&out[(long)(r0 + 8) * C + n]) =
                make_float2(acc[mf][nf][2] * inv8, acc[mf][nf][3] * inv8);
        }
    }
}

// ---------------------------------------------------------------------------
// proj + bias + residual: out = x + g_h @ w_proj + b_proj
// ---------------------------------------------------------------------------
__global__ __launch_bounds__(256) void proj_kernel(const float* __restrict__ x,
                                                   const float* __restrict__ w,
                                                   const float* __restrict__ bias,
                                                   float* __restrict__ out)
{
    const int n0 = blockIdx.x * 128;
    const int m0 = blockIdx.y * 128;
    float acc[4][4][4] = {};
    gemm_mma_core<true>(g_h + (long)m0 * C, w + n0, C, C, C, acc);

    const int lane = threadIdx.x & 31, warp = threadIdx.x >> 5;
    const int wm = warp >> 2, wn = warp & 3;
    #pragma unroll
    for (int mf = 0; mf < 4; mf++) {
        const int r0 = m0 + wm * 64 + mf * 16 + (lane >> 2);
        #pragma unroll
        for (int nf = 0; nf < 4; nf++) {
            const int n = n0 + wn * 32 + nf * 8 + 2 * (lane & 3);
            float b0 = bias[n], b1 = bias[n + 1];
            float2 x0 = *reinterpret_cast<const float2*>(&x[(long)r0 * C + n]);
            float2 x1 = *reinterpret_cast<const float2*>(&x[(long)(r0 + 8) * C + n]);
            *reinterpret_cast<float2*>(&out[(long)r0 * C + n]) =
                make_float2(acc[mf][nf][0] + b0 + x0.x, acc[mf][nf][1] + b1 + x0.y);
            *reinterpret_cast<float2*>(&out[(long)(r0 + 8) * C + n]) =
                make_float2(acc[mf][nf][2] + b0 + x1.x, acc[mf][nf][3] + b1 + x1.y);
        }
    }
}

// ---------------------------------------------------------------------------
extern "C" void kernel_launch(void* const* d_in, const int* in_sizes, int n_in,
                              void* d_out, int out_size)
{
    const float* x      = (const float*)d_in[0];
    const float* gamma  = (const float*)d_in[1];
    const float* beta   = (const float*)d_in[2];
    const float* w_qkv  = (const float*)d_in[3];
    const float* b_qkv  = (const float*)d_in[4];
    const float* w_proj = (const float*)d_in[5];
    const float* b_proj = (const float*)d_in[6];
    float* out = (float*)d_out;

    // Opt-in to >48KB dynamic smem (idempotent, capture-safe, no allocation).
    cudaFuncSetAttribute(qkv_gemm_kernel, cudaFuncAttributeMaxDynamicSharedMemorySize, SMEM_BYTES_NN);
    cudaFuncSetAttribute(scores_kernel,   cudaFuncAttributeMaxDynamicSharedMemorySize, SMEM_BYTES_NT);
    cudaFuncSetAttribute(av_kernel,       cudaFuncAttributeMaxDynamicSharedMemorySize, SMEM_BYTES_NN);
    cudaFuncSetAttribute(proj_kernel,     cudaFuncAttributeMaxDynamicSharedMemorySize, SMEM_BYTES_NN);

    zero_rowsum_kernel<<<NTOK / 256, 256>>>();
    groupnorm_kernel<<<Bb * G, 256>>>(x, gamma, beta);
    qkv_gemm_kernel<<<dim3(QKVN / 128, NTOK / 128), 256, SMEM_BYTES_NN>>>(w_qkv, b_qkv);
    scores_kernel<<<dim3(HW / 128, HW / 128, Bb), 256, SMEM_BYTES_NT>>>();
    av_kernel<<<dim3(C / 128, HW / 128, Bb), 256, SMEM_BYTES_NN>>>();
    proj_kernel<<<dim3(C / 128, NTOK / 128), 256, SMEM_BYTES_NN>>>(x, w_proj, b_proj, out);
}